// round 1
// baseline (speedup 1.0000x reference)
#include <cuda_runtime.h>

#define DHID  1024
#define NHEAD 16
#define HDIM  64
#define BATCH 4
#define ST    512
#define SI    576
#define SKV   1088
#define QSCALE 0.125f   // 64^-0.5
#define LN_EPS 1e-5f

// ---------------- scratch (device globals; allocation-free) ----------------
__device__ float g_ln_qt[BATCH * ST * DHID];
__device__ float g_ln_qi[BATCH * SI * DHID];
__device__ float g_ln_kt[BATCH * ST * DHID];
__device__ float g_ln_ki[BATCH * SI * DHID];
__device__ float g_Q_t[BATCH * NHEAD * ST * HDIM];   // [b][h][s][hd], pre-scaled
__device__ float g_Q_i[BATCH * NHEAD * SI * HDIM];
__device__ float g_K  [BATCH * NHEAD * SKV * HDIM];  // [b][h][kv][hd]
__device__ float g_Vt [BATCH * NHEAD * HDIM * SKV];  // [b][h][hd][kv]  (transposed V)
__device__ float g_O_t[BATCH * ST * DHID];           // [b][s][d] head-merged
__device__ float g_O_i[BATCH * SI * DHID];

// ---------------- LayerNorm: one block per row of 1024 ----------------
__global__ __launch_bounds__(256) void ln_kernel(const float* __restrict__ x,
                                                 const float* __restrict__ g,
                                                 const float* __restrict__ b,
                                                 float* __restrict__ y)
{
    const long long row = blockIdx.x;
    const int t = threadIdx.x;
    const float4 xv = reinterpret_cast<const float4*>(x + row * DHID)[t];

    float s  = xv.x + xv.y + xv.z + xv.w;
    float sq = xv.x * xv.x + xv.y * xv.y + xv.z * xv.z + xv.w * xv.w;

    __shared__ float red_s[8], red_q[8];
    #pragma unroll
    for (int o = 16; o > 0; o >>= 1) {
        s  += __shfl_xor_sync(0xffffffffu, s,  o);
        sq += __shfl_xor_sync(0xffffffffu, sq, o);
    }
    if ((t & 31) == 0) { red_s[t >> 5] = s; red_q[t >> 5] = sq; }
    __syncthreads();
    float ts = red_s[t & 7], tq = red_q[t & 7];
    #pragma unroll
    for (int o = 4; o > 0; o >>= 1) {
        ts += __shfl_xor_sync(0xffffffffu, ts, o);
        tq += __shfl_xor_sync(0xffffffffu, tq, o);
    }
    ts = __shfl_sync(0xffffffffu, ts, 0);
    tq = __shfl_sync(0xffffffffu, tq, 0);

    const float mean = ts * (1.0f / DHID);
    const float var  = tq * (1.0f / DHID) - mean * mean;
    const float rstd = rsqrtf(var + LN_EPS);

    const float4 gv = reinterpret_cast<const float4*>(g)[t];
    const float4 bv = reinterpret_cast<const float4*>(b)[t];
    float4 o;
    o.x = (xv.x - mean) * rstd * gv.x + bv.x;
    o.y = (xv.y - mean) * rstd * gv.y + bv.y;
    o.z = (xv.z - mean) * rstd * gv.z + bv.z;
    o.w = (xv.w - mean) * rstd * gv.w + bv.w;
    reinterpret_cast<float4*>(y + row * DHID)[t] = o;
}

// ---------------- generic SGEMM: C = (A · Btᵀ + bias) * alpha ----------------
// A: [M,K] row-major (+ z*sA), Bt: [N,K] row-major (+ z*sB), C += z*sC.
// Epilogue modes fuse layout transforms.
#define MODE_PLAIN   0  // C[m*N + n]
#define MODE_QSPLIT  1  // [b][h][s][hd], b=m/S, s=m%S, h=n/64, hd=n%64
#define MODE_KSPLIT  2  // [b][h][off+s][hd] into SKV axis
#define MODE_VT      3  // [b][h][hd][off+s]   (transposed V)
#define MODE_OMERGE  4  // batched (z=b*H+h): O[b][m][h*64+n]

__global__ __launch_bounds__(256) void gemm_kernel(
    const float* __restrict__ A, const float* __restrict__ Bt,
    float* __restrict__ C, const float* __restrict__ bias,
    int M, int N, int K,
    long long sA, long long sB, long long sC,
    int mode, int S, int off, float alpha)
{
    const int z = blockIdx.z;
    A  += (long long)z * sA;
    Bt += (long long)z * sB;
    C  += (long long)z * sC;

    __shared__ float As[8][128];
    __shared__ float Bs[8][128];

    const int bm = blockIdx.y * 128;
    const int bn = blockIdx.x * 128;
    const int tid = threadIdx.x;
    const int lrow = tid >> 1;
    const int lcol = (tid & 1) * 4;
    const int tx = tid & 15;   // 8 output cols each
    const int ty = tid >> 4;   // 8 output rows each

    float acc[8][8];
    #pragma unroll
    for (int i = 0; i < 8; i++)
        #pragma unroll
        for (int j = 0; j < 8; j++) acc[i][j] = 0.0f;

    const bool va = (bm + lrow) < M;
    const bool vb = (bn + lrow) < N;
    const float* Ap = A  + (long long)(bm + lrow) * K + lcol;
    const float* Bp = Bt + (long long)(bn + lrow) * K + lcol;

    for (int k0 = 0; k0 < K; k0 += 8) {
        float4 av = va ? *reinterpret_cast<const float4*>(Ap + k0) : make_float4(0.f,0.f,0.f,0.f);
        float4 bv = vb ? *reinterpret_cast<const float4*>(Bp + k0) : make_float4(0.f,0.f,0.f,0.f);
        __syncthreads();
        As[lcol+0][lrow] = av.x; As[lcol+1][lrow] = av.y;
        As[lcol+2][lrow] = av.z; As[lcol+3][lrow] = av.w;
        Bs[lcol+0][lrow] = bv.x; Bs[lcol+1][lrow] = bv.y;
        Bs[lcol+2][lrow] = bv.z; Bs[lcol+3][lrow] = bv.w;
        __syncthreads();
        #pragma unroll
        for (int k = 0; k < 8; k++) {
            float4 a0 = *reinterpret_cast<const float4*>(&As[k][ty * 8]);
            float4 a1 = *reinterpret_cast<const float4*>(&As[k][ty * 8 + 4]);
            float4 b0 = *reinterpret_cast<const float4*>(&Bs[k][tx * 8]);
            float4 b1 = *reinterpret_cast<const float4*>(&Bs[k][tx * 8 + 4]);
            float a[8] = {a0.x, a0.y, a0.z, a0.w, a1.x, a1.y, a1.z, a1.w};
            float b[8] = {b0.x, b0.y, b0.z, b0.w, b1.x, b1.y, b1.z, b1.w};
            #pragma unroll
            for (int i = 0; i < 8; i++)
                #pragma unroll
                for (int j = 0; j < 8; j++)
                    acc[i][j] = fmaf(a[i], b[j], acc[i][j]);
        }
    }

    const int rowbase = bm + ty * 8;
    const int colbase = bn + tx * 8;
    #pragma unroll
    for (int i = 0; i < 8; i++) {
        const int m = rowbase + i;
        if (m >= M) continue;
        #pragma unroll
        for (int j = 0; j < 8; j++) {
            const int n = colbase + j;
            if (n >= N) continue;
            float v = acc[i][j];
            if (bias) v += __ldg(&bias[n]);
            v *= alpha;
            long long idx;
            if (mode == MODE_PLAIN) {
                idx = (long long)m * N + n;
            } else if (mode == MODE_OMERGE) {
                const int b_ = z / NHEAD, h_ = z % NHEAD;
                idx = ((long long)b_ * S + m) * DHID + h_ * HDIM + n;
            } else {
                const int b_ = m / S, s_ = m - b_ * S;
                const int h_ = n >> 6, hd_ = n & 63;
                if (mode == MODE_QSPLIT)
                    idx = (((long long)(b_ * NHEAD + h_)) * S + s_) * HDIM + hd_;
                else if (mode == MODE_KSPLIT)
                    idx = (((long long)(b_ * NHEAD + h_)) * SKV + off + s_) * HDIM + hd_;
                else // MODE_VT
                    idx = (((long long)(b_ * NHEAD + h_)) * HDIM + hd_) * SKV + off + s_;
            }
            C[idx] = v;
        }
    }
}

// ---------------- softmax over rows of length SKV (in place) ----------------
__global__ __launch_bounds__(256) void softmax_kernel(float* __restrict__ w)
{
    const long long row = blockIdx.x;
    float* p = w + row * SKV;
    __shared__ float buf[SKV];
    __shared__ float red[8];
    const int t = threadIdx.x;

    float mx = -1e30f;
    for (int i = t; i < SKV; i += 256) { float v = p[i]; buf[i] = v; mx = fmaxf(mx, v); }
    #pragma unroll
    for (int o = 16; o > 0; o >>= 1) mx = fmaxf(mx, __shfl_xor_sync(0xffffffffu, mx, o));
    if ((t & 31) == 0) red[t >> 5] = mx;
    __syncthreads();
    mx = red[t & 7];
    #pragma unroll
    for (int o = 4; o > 0; o >>= 1) mx = fmaxf(mx, __shfl_xor_sync(0xffffffffu, mx, o));
    mx = __shfl_sync(0xffffffffu, mx, 0);
    __syncthreads();

    float sum = 0.0f;
    for (int i = t; i < SKV; i += 256) { float e = __expf(buf[i] - mx); buf[i] = e; sum += e; }
    #pragma unroll
    for (int o = 16; o > 0; o >>= 1) sum += __shfl_xor_sync(0xffffffffu, sum, o);
    if ((t & 31) == 0) red[t >> 5] = sum;
    __syncthreads();
    sum = red[t & 7];
    #pragma unroll
    for (int o = 4; o > 0; o >>= 1) sum += __shfl_xor_sync(0xffffffffu, sum, o);
    sum = __shfl_sync(0xffffffffu, sum, 0);

    const float inv = 1.0f / sum;
    for (int i = t; i < SKV; i += 256) p[i] = buf[i] * inv;
}

// ---------------- host orchestration ----------------
static inline void launch_gemm(const float* A, const float* Bt, float* C, const float* bias,
                               int M, int N, int K,
                               long long sA, long long sB, long long sC, int nb,
                               int mode, int S, int off, float alpha)
{
    dim3 grid((N + 127) / 128, (M + 127) / 128, nb);
    gemm_kernel<<<grid, 256>>>(A, Bt, C, bias, M, N, K, sA, sB, sC, mode, S, off, alpha);
}

extern "C" void kernel_launch(void* const* d_in, const int* in_sizes, int n_in,
                              void* d_out, int out_size)
{
    const float* q_text  = (const float*)d_in[0];
    const float* q_image = (const float*)d_in[1];
    const float* k_text  = (const float*)d_in[2];
    const float* k_image = (const float*)d_in[3];
    const float* Wq_t = (const float*)d_in[4];  const float* bq_t = (const float*)d_in[5];
    const float* Wk_t = (const float*)d_in[6];  const float* bk_t = (const float*)d_in[7];
    const float* Wv_t = (const float*)d_in[8];  const float* bv_t = (const float*)d_in[9];
    const float* Wq_i = (const float*)d_in[10]; const float* bq_i = (const float*)d_in[11];
    const float* Wk_i = (const float*)d_in[12]; const float* bk_i = (const float*)d_in[13];
    const float* Wv_i = (const float*)d_in[14]; const float* bv_i = (const float*)d_in[15];
    const float* lng_t = (const float*)d_in[16]; const float* lnb_t = (const float*)d_in[17];
    const float* lng_i = (const float*)d_in[18]; const float* lnb_i = (const float*)d_in[19];
    const float* Wo = (const float*)d_in[20]; const float* bo = (const float*)d_in[21];

    float* out = (float*)d_out;
    const long long OUT_T = 0;
    const long long OUT_I = (long long)BATCH * ST * DHID;                 // 2097152
    const long long W_T   = OUT_I + (long long)BATCH * SI * DHID;         // 4456448
    const long long W_I   = W_T + (long long)BATCH * NHEAD * ST * SKV;    // 40108032

    float *pLNQT, *pLNQI, *pLNKT, *pLNKI, *pQT, *pQI, *pK, *pVT, *pOT, *pOI;
    cudaGetSymbolAddress((void**)&pLNQT, g_ln_qt);
    cudaGetSymbolAddress((void**)&pLNQI, g_ln_qi);
    cudaGetSymbolAddress((void**)&pLNKT, g_ln_kt);
    cudaGetSymbolAddress((void**)&pLNKI, g_ln_ki);
    cudaGetSymbolAddress((void**)&pQT,   g_Q_t);
    cudaGetSymbolAddress((void**)&pQI,   g_Q_i);
    cudaGetSymbolAddress((void**)&pK,    g_K);
    cudaGetSymbolAddress((void**)&pVT,   g_Vt);
    cudaGetSymbolAddress((void**)&pOT,   g_O_t);
    cudaGetSymbolAddress((void**)&pOI,   g_O_i);

    // 1) LayerNorms
    ln_kernel<<<BATCH * ST, 256>>>(q_text,  lng_t, lnb_t, pLNQT);
    ln_kernel<<<BATCH * SI, 256>>>(q_image, lng_i, lnb_i, pLNQI);
    ln_kernel<<<BATCH * ST, 256>>>(k_text,  lng_t, lnb_t, pLNKT);
    ln_kernel<<<BATCH * SI, 256>>>(k_image, lng_i, lnb_i, pLNKI);

    // 2) Projections (fused head split / concat / V-transpose / Q-scale)
    launch_gemm(pLNQT, Wq_t, pQT, bq_t, BATCH*ST, DHID, DHID, 0,0,0, 1, MODE_QSPLIT, ST, 0,   QSCALE);
    launch_gemm(pLNQI, Wq_i, pQI, bq_i, BATCH*SI, DHID, DHID, 0,0,0, 1, MODE_QSPLIT, SI, 0,   QSCALE);
    launch_gemm(pLNKT, Wk_t, pK,  bk_t, BATCH*ST, DHID, DHID, 0,0,0, 1, MODE_KSPLIT, ST, 0,   1.0f);
    launch_gemm(pLNKI, Wk_i, pK,  bk_i, BATCH*SI, DHID, DHID, 0,0,0, 1, MODE_KSPLIT, SI, ST,  1.0f);
    launch_gemm(pLNKT, Wv_t, pVT, bv_t, BATCH*ST, DHID, DHID, 0,0,0, 1, MODE_VT,     ST, 0,   1.0f);
    launch_gemm(pLNKI, Wv_i, pVT, bv_i, BATCH*SI, DHID, DHID, 0,0,0, 1, MODE_VT,     SI, ST,  1.0f);

    // 3) Scores = Q · Kᵀ  (batched over b*h = 64), written raw into w regions
    launch_gemm(pQT, pK, out + W_T, nullptr, ST, SKV, HDIM,
                (long long)ST * HDIM, (long long)SKV * HDIM, (long long)ST * SKV, BATCH*NHEAD,
                MODE_PLAIN, 0, 0, 1.0f);
    launch_gemm(pQI, pK, out + W_I, nullptr, SI, SKV, HDIM,
                (long long)SI * HDIM, (long long)SKV * HDIM, (long long)SI * SKV, BATCH*NHEAD,
                MODE_PLAIN, 0, 0, 1.0f);

    // 4) Softmax in place over all w rows (w_t and w_i are contiguous)
    softmax_kernel<<<BATCH * NHEAD * (ST + SI), 256>>>(out + W_T);

    // 5) O = w · V (via transposed V), head-merge fused in store
    launch_gemm(out + W_T, pVT, pOT, nullptr, ST, HDIM, SKV,
                (long long)ST * SKV, (long long)HDIM * SKV, 0, BATCH*NHEAD,
                MODE_OMERGE, ST, 0, 1.0f);
    launch_gemm(out + W_I, pVT, pOI, nullptr, SI, HDIM, SKV,
                (long long)SI * SKV, (long long)HDIM * SKV, 0, BATCH*NHEAD,
                MODE_OMERGE, SI, 0, 1.0f);

    // 6) Output projection
    launch_gemm(pOT, Wo, out + OUT_T, bo, BATCH*ST, DHID, DHID, 0,0,0, 1, MODE_PLAIN, 0, 0, 1.0f);
    launch_gemm(pOI, Wo, out + OUT_I, bo, BATCH*SI, DHID, DHID, 0,0,0, 1, MODE_PLAIN, 0, 0, 1.0f);

    (void)in_sizes; (void)n_in; (void)out_size;
}

// round 3
// speedup vs baseline: 2.4586x; 2.4586x over previous
#include <cuda_runtime.h>
#include <cstdint>

#define DHID  1024
#define NHEAD 16
#define HDIM  64
#define BATCH 4
#define ST    512
#define SI    576
#define SKV   1088
#define QSCALE 0.125f
#define LN_EPS 1e-5f

#define SC_STRIDE 1092   // scores row stride (floats): 1092%32==4 -> conflict-free frags
#define QK_STRIDE 68     // Q/K tile row stride: 68%32==4
#define V_STRIDE  72     // V tile row stride: 72%32==8

// ---------------- scratch (device globals; allocation-free) ----------------
__device__ float g_ln_qt[BATCH * ST * DHID];
__device__ float g_ln_qi[BATCH * SI * DHID];
__device__ float g_ln_kt[BATCH * ST * DHID];
__device__ float g_ln_ki[BATCH * SI * DHID];
__device__ float g_Q_t[BATCH * NHEAD * ST * HDIM];   // [z][s][hd], pre-scaled
__device__ float g_Q_i[BATCH * NHEAD * SI * HDIM];
__device__ float g_K  [BATCH * NHEAD * SKV * HDIM];  // [z][kv][hd]
__device__ float g_V  [BATCH * NHEAD * SKV * HDIM];  // [z][kv][hd]
__device__ float g_O_t[BATCH * ST * DHID];           // [b][s][d] head-merged
__device__ float g_O_i[BATCH * SI * DHID];

// ---------------- helpers ----------------
__device__ __forceinline__ uint32_t f2tf(float f) {
    uint32_t u; asm("cvt.rna.tf32.f32 %0, %1;" : "=r"(u) : "f"(f)); return u;
}
__device__ __forceinline__ void mma_tf32(float* d, const uint32_t* a, const uint32_t* b) {
    asm volatile("mma.sync.aligned.m16n8k8.row.col.f32.tf32.tf32.f32 "
                 "{%0,%1,%2,%3}, {%4,%5,%6,%7}, {%8,%9}, {%0,%1,%2,%3};"
                 : "+f"(d[0]), "+f"(d[1]), "+f"(d[2]), "+f"(d[3])
                 : "r"(a[0]), "r"(a[1]), "r"(a[2]), "r"(a[3]), "r"(b[0]), "r"(b[1]));
}

// ---------------- LayerNorm ----------------
__global__ __launch_bounds__(256) void ln_kernel(const float* __restrict__ x,
                                                 const float* __restrict__ g,
                                                 const float* __restrict__ b,
                                                 float* __restrict__ y)
{
    const long long row = blockIdx.x;
    const int t = threadIdx.x;
    const float4 xv = reinterpret_cast<const float4*>(x + row * DHID)[t];

    float s  = xv.x + xv.y + xv.z + xv.w;
    float sq = xv.x * xv.x + xv.y * xv.y + xv.z * xv.z + xv.w * xv.w;

    __shared__ float red_s[8], red_q[8];
    #pragma unroll
    for (int o = 16; o > 0; o >>= 1) {
        s  += __shfl_xor_sync(0xffffffffu, s,  o);
        sq += __shfl_xor_sync(0xffffffffu, sq, o);
    }
    if ((t & 31) == 0) { red_s[t >> 5] = s; red_q[t >> 5] = sq; }
    __syncthreads();
    float ts = red_s[t & 7], tq = red_q[t & 7];
    #pragma unroll
    for (int o = 4; o > 0; o >>= 1) {
        ts += __shfl_xor_sync(0xffffffffu, ts, o);
        tq += __shfl_xor_sync(0xffffffffu, tq, o);
    }
    ts = __shfl_sync(0xffffffffu, ts, 0);
    tq = __shfl_sync(0xffffffffu, tq, 0);

    const float mean = ts * (1.0f / DHID);
    const float rstd = rsqrtf(tq * (1.0f / DHID) - mean * mean + LN_EPS);

    const float4 gv = reinterpret_cast<const float4*>(g)[t];
    const float4 bv = reinterpret_cast<const float4*>(b)[t];
    float4 o;
    o.x = (xv.x - mean) * rstd * gv.x + bv.x;
    o.y = (xv.y - mean) * rstd * gv.y + bv.y;
    o.z = (xv.z - mean) * rstd * gv.z + bv.z;
    o.w = (xv.w - mean) * rstd * gv.w + bv.w;
    reinterpret_cast<float4*>(y + row * DHID)[t] = o;
}

// ---------------- tf32 GEMM: C = (A · Btᵀ + bias) * alpha ----------------
// N = K = 1024 fixed. M multiple of 128. Block tile 128x128, K-step 32.
#define MODE_PLAIN  0   // C[m*1024 + n]
#define MODE_QSPLIT 1   // [z=b*16+h][s][hd]
#define MODE_KV     2   // [z][off+s][hd] (SKV axis)

template<int MODE>
__global__ __launch_bounds__(256) void gemm_tf32(
    const float* __restrict__ A, const float* __restrict__ Bt,
    float* __restrict__ C, const float* __restrict__ bias,
    int S, int off, float alpha)
{
    __shared__ uint32_t As[128 * 36];
    __shared__ uint32_t Bs[128 * 36];

    const int bm = blockIdx.y * 128;
    const int bn = blockIdx.x * 128;
    const int tid  = threadIdx.x;
    const int w    = tid >> 5;
    const int lane = tid & 31;
    const int gid  = lane >> 2;
    const int ctid = lane & 3;
    const int wm = (w & 1) * 64;    // 2 m-warps
    const int wn = (w >> 1) * 32;   // 4 n-warps

    const int lr = tid >> 3;         // 0..31
    const int lc = (tid & 7) * 4;    // 0,4,..,28

    float acc[4][4][4];
    #pragma unroll
    for (int i = 0; i < 4; i++)
        #pragma unroll
        for (int j = 0; j < 4; j++)
            #pragma unroll
            for (int e = 0; e < 4; e++) acc[i][j][e] = 0.0f;

    for (int k0 = 0; k0 < DHID; k0 += 32) {
        float4 av[4], bv[4];
        #pragma unroll
        for (int p = 0; p < 4; p++) {
            av[p] = *reinterpret_cast<const float4*>(&A [(long long)(bm + lr + p * 32) * DHID + k0 + lc]);
            bv[p] = *reinterpret_cast<const float4*>(&Bt[(long long)(bn + lr + p * 32) * DHID + k0 + lc]);
        }
        __syncthreads();
        #pragma unroll
        for (int p = 0; p < 4; p++) {
            uint4 ua = make_uint4(f2tf(av[p].x), f2tf(av[p].y), f2tf(av[p].z), f2tf(av[p].w));
            uint4 ub = make_uint4(f2tf(bv[p].x), f2tf(bv[p].y), f2tf(bv[p].z), f2tf(bv[p].w));
            *reinterpret_cast<uint4*>(&As[(lr + p * 32) * 36 + lc]) = ua;
            *reinterpret_cast<uint4*>(&Bs[(lr + p * 32) * 36 + lc]) = ub;
        }
        __syncthreads();

        #pragma unroll
        for (int ks = 0; ks < 4; ks++) {
            const int kk = ks * 8;
            uint32_t af[4][4], bf[4][2];
            #pragma unroll
            for (int mf = 0; mf < 4; mf++) {
                const int r = wm + mf * 16 + gid;
                af[mf][0] = As[r       * 36 + kk + ctid];
                af[mf][1] = As[(r + 8) * 36 + kk + ctid];
                af[mf][2] = As[r       * 36 + kk + ctid + 4];
                af[mf][3] = As[(r + 8) * 36 + kk + ctid + 4];
            }
            #pragma unroll
            for (int nf = 0; nf < 4; nf++) {
                const int c = wn + nf * 8 + gid;
                bf[nf][0] = Bs[c * 36 + kk + ctid];
                bf[nf][1] = Bs[c * 36 + kk + ctid + 4];
            }
            #pragma unroll
            for (int mf = 0; mf < 4; mf++)
                #pragma unroll
                for (int nf = 0; nf < 4; nf++)
                    mma_tf32(acc[mf][nf], af[mf], bf[nf]);
        }
    }

    // epilogue (all modes keep n-adjacency -> float2 stores)
    #pragma unroll
    for (int mf = 0; mf < 4; mf++) {
        #pragma unroll
        for (int nf = 0; nf < 4; nf++) {
            const int r0 = bm + wm + mf * 16 + gid;
            const int c0 = bn + wn + nf * 8 + 2 * ctid;
            const float b0 = bias ? bias[c0]     : 0.0f;
            const float b1 = bias ? bias[c0 + 1] : 0.0f;
            float2 v0, v1;
            v0.x = (acc[mf][nf][0] + b0) * alpha;
            v0.y = (acc[mf][nf][1] + b1) * alpha;
            v1.x = (acc[mf][nf][2] + b0) * alpha;
            v1.y = (acc[mf][nf][3] + b1) * alpha;
            long long i0, i1;
            if (MODE == MODE_PLAIN) {
                i0 = (long long)r0 * DHID + c0;
                i1 = (long long)(r0 + 8) * DHID + c0;
            } else {
                const int h  = c0 >> 6, hd = c0 & 63;
                const int b_  = r0 / S, s0 = r0 - b_ * S;
                const int b_2 = (r0 + 8) / S, s1 = (r0 + 8) - b_2 * S;
                if (MODE == MODE_QSPLIT) {
                    i0 = (((long long)(b_  * NHEAD + h)) * S + s0) * HDIM + hd;
                    i1 = (((long long)(b_2 * NHEAD + h)) * S + s1) * HDIM + hd;
                } else { // MODE_KV
                    i0 = (((long long)(b_  * NHEAD + h)) * SKV + off + s0) * HDIM + hd;
                    i1 = (((long long)(b_2 * NHEAD + h)) * SKV + off + s1) * HDIM + hd;
                }
            }
            *reinterpret_cast<float2*>(&C[i0]) = v0;
            *reinterpret_cast<float2*>(&C[i1]) = v1;
        }
    }
}

// ---------------- fused attention: scores + softmax + w-write + w·V ----------------
// Block: 32 q-rows of one (b,h). Full 1088-wide score row kept in smem.
__global__ __launch_bounds__(256) void attn_kernel(
    const float* __restrict__ Q,    // [64][Sq][64] (pre-scaled)
    const float* __restrict__ Kg,   // [64][SKV][64]
    const float* __restrict__ Vg,   // [64][SKV][64]
    float* __restrict__ Wout,       // w region base, rows [z*Sq + q][SKV]
    float* __restrict__ O,          // [B][Sq][1024]
    int Sq)
{
    extern __shared__ char sm[];
    float*    Sc  = reinterpret_cast<float*>(sm);                              // 32 x SC_STRIDE
    uint32_t* Qs  = reinterpret_cast<uint32_t*>(sm + 32 * SC_STRIDE * 4);      // 32 x QK_STRIDE
    uint32_t* KVs = reinterpret_cast<uint32_t*>(sm + (32 * SC_STRIDE + 32 * QK_STRIDE) * 4); // 128 x V_STRIDE max

    const int z = blockIdx.y;
    const int qbase = blockIdx.x * 32;
    const int tid  = threadIdx.x;
    const int w    = tid >> 5;
    const int lane = tid & 31;
    const int gid  = lane >> 2;
    const int ctid = lane & 3;
    const int b = z >> 4, h = z & 15;

    // load Q tile 32x64 (tf32)
    for (int i = tid; i < 32 * 16; i += 256) {
        const int r = i >> 4, c4 = (i & 15) * 4;
        float4 v = *reinterpret_cast<const float4*>(&Q[((long long)z * Sq + qbase + r) * HDIM + c4]);
        *reinterpret_cast<uint4*>(&Qs[r * QK_STRIDE + c4]) =
            make_uint4(f2tf(v.x), f2tf(v.y), f2tf(v.z), f2tf(v.w));
    }

    // ---- phase 1: scores = Q · K^T ----
    for (int cb = 0; cb < SKV; cb += 128) {
        const int cw = min(128, SKV - cb);
        __syncthreads();
        for (int i = tid; i < cw * 16; i += 256) {
            const int r = i >> 4, c4 = (i & 15) * 4;
            float4 v = *reinterpret_cast<const float4*>(&Kg[((long long)z * SKV + cb + r) * HDIM + c4]);
            *reinterpret_cast<uint4*>(&KVs[r * QK_STRIDE + c4]) =
                make_uint4(f2tf(v.x), f2tf(v.y), f2tf(v.z), f2tf(v.w));
        }
        __syncthreads();

        const int nfr = cw >> 6;          // 2 (full) or 1 (tail)
        const int wnb = w * (cw >> 3);    // per-warp col base in chunk
        float acc[2][2][4];
        #pragma unroll
        for (int mf = 0; mf < 2; mf++)
            #pragma unroll
            for (int nf = 0; nf < 2; nf++)
                #pragma unroll
                for (int e = 0; e < 4; e++) acc[mf][nf][e] = 0.0f;

        #pragma unroll
        for (int ks = 0; ks < 8; ks++) {
            const int kk = ks * 8;
            uint32_t af[2][4], bf[2][2];
            #pragma unroll
            for (int mf = 0; mf < 2; mf++) {
                const int r = mf * 16 + gid;
                af[mf][0] = Qs[r       * QK_STRIDE + kk + ctid];
                af[mf][1] = Qs[(r + 8) * QK_STRIDE + kk + ctid];
                af[mf][2] = Qs[r       * QK_STRIDE + kk + ctid + 4];
                af[mf][3] = Qs[(r + 8) * QK_STRIDE + kk + ctid + 4];
            }
            for (int nf = 0; nf < nfr; nf++) {
                const int c = wnb + nf * 8 + gid;
                bf[nf][0] = KVs[c * QK_STRIDE + kk + ctid];
                bf[nf][1] = KVs[c * QK_STRIDE + kk + ctid + 4];
            }
            #pragma unroll
            for (int mf = 0; mf < 2; mf++)
                for (int nf = 0; nf < nfr; nf++)
                    mma_tf32(acc[mf][nf], af[mf], bf[nf]);
        }
        // store scores to smem
        #pragma unroll
        for (int mf = 0; mf < 2; mf++)
            for (int nf = 0; nf < nfr; nf++) {
                const int r0 = mf * 16 + gid;
                const int c0 = cb + wnb + nf * 8 + 2 * ctid;
                *reinterpret_cast<float2*>(&Sc[r0 * SC_STRIDE + c0])       = make_float2(acc[mf][nf][0], acc[mf][nf][1]);
                *reinterpret_cast<float2*>(&Sc[(r0 + 8) * SC_STRIDE + c0]) = make_float2(acc[mf][nf][2], acc[mf][nf][3]);
            }
    }
    __syncthreads();

    // ---- phase 2: softmax + write w + convert in place to tf32 ----
    {
        const int r = tid >> 3, l8 = tid & 7;
        float mx = -1e30f;
        for (int i = l8; i < SKV; i += 8) mx = fmaxf(mx, Sc[r * SC_STRIDE + i]);
        #pragma unroll
        for (int o = 4; o > 0; o >>= 1) mx = fmaxf(mx, __shfl_xor_sync(0xffffffffu, mx, o));
        float sum = 0.0f;
        for (int i = l8; i < SKV; i += 8) {
            float e = __expf(Sc[r * SC_STRIDE + i] - mx);
            Sc[r * SC_STRIDE + i] = e;
            sum += e;
        }
        #pragma unroll
        for (int o = 4; o > 0; o >>= 1) sum += __shfl_xor_sync(0xffffffffu, sum, o);
        const float inv = 1.0f / sum;
        float* wrow = Wout + ((long long)z * Sq + qbase + r) * SKV;
        uint32_t* Scu = reinterpret_cast<uint32_t*>(Sc);
        for (int i = l8; i < SKV; i += 8) {
            const float v = Sc[r * SC_STRIDE + i] * inv;
            wrow[i] = v;
            Scu[r * SC_STRIDE + i] = f2tf(v);
        }
    }

    // ---- phase 3: O = w · V ----
    const uint32_t* Scu = reinterpret_cast<const uint32_t*>(Sc);
    float oacc[2][4];
    #pragma unroll
    for (int mf = 0; mf < 2; mf++)
        #pragma unroll
        for (int e = 0; e < 4; e++) oacc[mf][e] = 0.0f;
    const int wn3 = w * 8;   // per-warp hd strip

    for (int cb = 0; cb < SKV; cb += 128) {
        const int cw = min(128, SKV - cb);
        __syncthreads();
        for (int i = tid; i < cw * 16; i += 256) {
            const int r = i >> 4, c4 = (i & 15) * 4;
            float4 v = *reinterpret_cast<const float4*>(&Vg[((long long)z * SKV + cb + r) * HDIM + c4]);
            *reinterpret_cast<uint4*>(&KVs[r * V_STRIDE + c4]) =
                make_uint4(f2tf(v.x), f2tf(v.y), f2tf(v.z), f2tf(v.w));
        }
        __syncthreads();

        const int ksteps = cw >> 3;
        for (int ks = 0; ks < ksteps; ks++) {
            const int kk = ks * 8;
            uint32_t af[2][4], bf[2];
            #pragma unroll
            for (int mf = 0; mf < 2; mf++) {
                const int r = mf * 16 + gid;
                af[mf][0] = Scu[r       * SC_STRIDE + cb + kk + ctid];
                af[mf][1] = Scu[(r + 8) * SC_STRIDE + cb + kk + ctid];
                af[mf][2] = Scu[r       * SC_STRIDE + cb + kk + ctid + 4];
                af[mf][3] = Scu[(r + 8) * SC_STRIDE + cb + kk + ctid + 4];
            }
            bf[0] = KVs[(kk + ctid)     * V_STRIDE + wn3 + gid];
            bf[1] = KVs[(kk + ctid + 4) * V_STRIDE + wn3 + gid];
            #pragma unroll
            for (int mf = 0; mf < 2; mf++)
                mma_tf32(oacc[mf], af[mf], bf);
        }
    }

    // epilogue: head-merged O
    #pragma unroll
    for (int mf = 0; mf < 2; mf++) {
        const int r0 = qbase + mf * 16 + gid;
        const int c0 = h * HDIM + wn3 + 2 * ctid;
        *reinterpret_cast<float2*>(&O[((long long)b * Sq + r0) * DHID + c0])     = make_float2(oacc[mf][0], oacc[mf][1]);
        *reinterpret_cast<float2*>(&O[((long long)b * Sq + r0 + 8) * DHID + c0]) = make_float2(oacc[mf][2], oacc[mf][3]);
    }
}

// ---------------- host orchestration ----------------
#define ATTN_SMEM ((32 * SC_STRIDE + 32 * QK_STRIDE + 128 * V_STRIDE) * 4)

extern "C" void kernel_launch(void* const* d_in, const int* in_sizes, int n_in,
                              void* d_out, int out_size)
{
    const float* q_text  = (const float*)d_in[0];
    const float* q_image = (const float*)d_in[1];
    const float* k_text  = (const float*)d_in[2];
    const float* k_image = (const float*)d_in[3];
    const float* Wq_t = (const float*)d_in[4];  const float* bq_t = (const float*)d_in[5];
    const float* Wk_t = (const float*)d_in[6];  const float* bk_t = (const float*)d_in[7];
    const float* Wv_t = (const float*)d_in[8];  const float* bv_t = (const float*)d_in[9];
    const float* Wq_i = (const float*)d_in[10]; const float* bq_i = (const float*)d_in[11];
    const float* Wk_i = (const float*)d_in[12]; const float* bk_i = (const float*)d_in[13];
    const float* Wv_i = (const float*)d_in[14]; const float* bv_i = (const float*)d_in[15];
    const float* lng_t = (const float*)d_in[16]; const float* lnb_t = (const float*)d_in[17];
    const float* lng_i = (const float*)d_in[18]; const float* lnb_i = (const float*)d_in[19];
    const float* Wo = (const float*)d_in[20]; const float* bo = (const float*)d_in[21];

    float* out = (float*)d_out;
    const long long OUT_T = 0;
    const long long OUT_I = (long long)BATCH * ST * DHID;
    const long long W_T   = OUT_I + (long long)BATCH * SI * DHID;
    const long long W_I   = W_T + (long long)BATCH * NHEAD * ST * SKV;

    float *pLNQT, *pLNQI, *pLNKT, *pLNKI, *pQT, *pQI, *pK, *pV, *pOT, *pOI;
    cudaGetSymbolAddress((void**)&pLNQT, g_ln_qt);
    cudaGetSymbolAddress((void**)&pLNQI, g_ln_qi);
    cudaGetSymbolAddress((void**)&pLNKT, g_ln_kt);
    cudaGetSymbolAddress((void**)&pLNKI, g_ln_ki);
    cudaGetSymbolAddress((void**)&pQT,   g_Q_t);
    cudaGetSymbolAddress((void**)&pQI,   g_Q_i);
    cudaGetSymbolAddress((void**)&pK,    g_K);
    cudaGetSymbolAddress((void**)&pV,    g_V);
    cudaGetSymbolAddress((void**)&pOT,   g_O_t);
    cudaGetSymbolAddress((void**)&pOI,   g_O_i);

    cudaFuncSetAttribute(attn_kernel, cudaFuncAttributeMaxDynamicSharedMemorySize, ATTN_SMEM);

    // 1) LayerNorms
    ln_kernel<<<BATCH * ST, 256>>>(q_text,  lng_t, lnb_t, pLNQT);
    ln_kernel<<<BATCH * SI, 256>>>(q_image, lng_i, lnb_i, pLNQI);
    ln_kernel<<<BATCH * ST, 256>>>(k_text,  lng_t, lnb_t, pLNKT);
    ln_kernel<<<BATCH * SI, 256>>>(k_image, lng_i, lnb_i, pLNKI);

    // 2) Projections (tf32 tensor-core GEMMs, fused layout transforms)
    {
        dim3 gT(DHID / 128, (BATCH * ST) / 128);   // 8 x 16
        dim3 gI(DHID / 128, (BATCH * SI) / 128);   // 8 x 18
        gemm_tf32<MODE_QSPLIT><<<gT, 256>>>(pLNQT, Wq_t, pQT, bq_t, ST, 0,  QSCALE);
        gemm_tf32<MODE_QSPLIT><<<gI, 256>>>(pLNQI, Wq_i, pQI, bq_i, SI, 0,  QSCALE);
        gemm_tf32<MODE_KV>    <<<gT, 256>>>(pLNKT, Wk_t, pK,  bk_t, ST, 0,  1.0f);
        gemm_tf32<MODE_KV>    <<<gI, 256>>>(pLNKI, Wk_i, pK,  bk_i, SI, ST, 1.0f);
        gemm_tf32<MODE_KV>    <<<gT, 256>>>(pLNKT, Wv_t, pV,  bv_t, ST, 0,  1.0f);
        gemm_tf32<MODE_KV>    <<<gI, 256>>>(pLNKI, Wv_i, pV,  bv_i, SI, ST, 1.0f);
    }

    // 3) Fused attention (scores + softmax + w write + w·V)
    {
        dim3 gT(ST / 32, BATCH * NHEAD);   // 16 x 64
        dim3 gI(SI / 32, BATCH * NHEAD);   // 18 x 64
        attn_kernel<<<gT, 256, ATTN_SMEM>>>(pQT, pK, pV, out + W_T, pOT, ST);
        attn_kernel<<<gI, 256, ATTN_SMEM>>>(pQI, pK, pV, out + W_I, pOI, SI);
    }

    // 4) Output projection
    {
        dim3 gT(DHID / 128, (BATCH * ST) / 128);
        dim3 gI(DHID / 128, (BATCH * SI) / 128);
        gemm_tf32<MODE_PLAIN><<<gT, 256>>>(pOT, Wo, out + OUT_T, bo, 0, 0, 1.0f);
        gemm_tf32<MODE_PLAIN><<<gI, 256>>>(pOI, Wo, out + OUT_I, bo, 0, 0, 1.0f);
    }

    (void)in_sizes; (void)n_in; (void)out_size;
}

// round 4
// speedup vs baseline: 3.8764x; 1.5767x over previous
#include <cuda_runtime.h>
#include <cstdint>

#define DHID  1024
#define NHEAD 16
#define HDIM  64
#define BATCH 4
#define ST    512
#define SI    576
#define SKV   1088
#define QSCALE 0.125f
#define LN_EPS 1e-5f

#define SC_STRIDE 1092   // scores row stride (floats), %32==4 -> conflict-free frags
#define Q_STRIDE  68     // Q staging stride, %32==4
#define KV_STRIDE 72     // K/V chunk stride, %32==8

// ---------------- scratch (device globals; allocation-free) ----------------
__device__ float g_ln_qt[BATCH * ST * DHID];
__device__ float g_ln_qi[BATCH * SI * DHID];
__device__ float g_ln_kt[BATCH * ST * DHID];
__device__ float g_ln_ki[BATCH * SI * DHID];
__device__ float g_Q_t[BATCH * NHEAD * ST * HDIM];   // [z][s][hd], pre-scaled
__device__ float g_Q_i[BATCH * NHEAD * SI * HDIM];
__device__ float g_K  [BATCH * NHEAD * SKV * HDIM];  // [z][kv][hd]
__device__ float g_V  [BATCH * NHEAD * SKV * HDIM];  // [z][kv][hd]
__device__ float g_O_t[BATCH * ST * DHID];           // [b][s][d] head-merged
__device__ float g_O_i[BATCH * SI * DHID];

// ---------------- helpers ----------------
__device__ __forceinline__ uint32_t f2tf(float f) {
    uint32_t u; asm("cvt.rna.tf32.f32 %0, %1;" : "=r"(u) : "f"(f)); return u;
}
__device__ __forceinline__ void mma_tf32(float* d, const uint32_t* a, const uint32_t* b) {
    asm volatile("mma.sync.aligned.m16n8k8.row.col.f32.tf32.tf32.f32 "
                 "{%0,%1,%2,%3}, {%4,%5,%6,%7}, {%8,%9}, {%0,%1,%2,%3};"
                 : "+f"(d[0]), "+f"(d[1]), "+f"(d[2]), "+f"(d[3])
                 : "r"(a[0]), "r"(a[1]), "r"(a[2]), "r"(a[3]), "r"(b[0]), "r"(b[1]));
}
__device__ __forceinline__ uint32_t s2u(const void* p) {
    return (uint32_t)__cvta_generic_to_shared(p);
}
__device__ __forceinline__ void cp16(uint32_t dst, const void* src) {
    asm volatile("cp.async.cg.shared.global [%0], [%1], 16;" :: "r"(dst), "l"(src));
}
__device__ __forceinline__ void cp_commit() {
    asm volatile("cp.async.commit_group;");
}
__device__ __forceinline__ void cp_wait0() {
    asm volatile("cp.async.wait_group 0;" ::: "memory");
}

// ---------------- LayerNorm (4 jobs in one launch) ----------------
struct LnJob { const float* x; const float* g; const float* b; float* y; int rows; };
struct LnBatch { LnJob j[4]; };

__global__ __launch_bounds__(256) void ln_multi(LnBatch batch)
{
    const LnJob jb = batch.j[blockIdx.y];
    const int row = blockIdx.x;
    if (row >= jb.rows) return;
    const int t = threadIdx.x;
    const float4 xv = reinterpret_cast<const float4*>(jb.x + (long long)row * DHID)[t];

    float s  = xv.x + xv.y + xv.z + xv.w;
    float sq = xv.x * xv.x + xv.y * xv.y + xv.z * xv.z + xv.w * xv.w;

    __shared__ float red_s[8], red_q[8];
    #pragma unroll
    for (int o = 16; o > 0; o >>= 1) {
        s  += __shfl_xor_sync(0xffffffffu, s,  o);
        sq += __shfl_xor_sync(0xffffffffu, sq, o);
    }
    if ((t & 31) == 0) { red_s[t >> 5] = s; red_q[t >> 5] = sq; }
    __syncthreads();
    float ts = red_s[t & 7], tq = red_q[t & 7];
    #pragma unroll
    for (int o = 4; o > 0; o >>= 1) {
        ts += __shfl_xor_sync(0xffffffffu, ts, o);
        tq += __shfl_xor_sync(0xffffffffu, tq, o);
    }
    ts = __shfl_sync(0xffffffffu, ts, 0);
    tq = __shfl_sync(0xffffffffu, tq, 0);

    const float mean = ts * (1.0f / DHID);
    const float rstd = rsqrtf(tq * (1.0f / DHID) - mean * mean + LN_EPS);

    const float4 gv = reinterpret_cast<const float4*>(jb.g)[t];
    const float4 bv = reinterpret_cast<const float4*>(jb.b)[t];
    float4 o;
    o.x = (xv.x - mean) * rstd * gv.x + bv.x;
    o.y = (xv.y - mean) * rstd * gv.y + bv.y;
    o.z = (xv.z - mean) * rstd * gv.z + bv.z;
    o.w = (xv.w - mean) * rstd * gv.w + bv.w;
    reinterpret_cast<float4*>(jb.y + (long long)row * DHID)[t] = o;
}

// ---------------- batched tf32 GEMM: C = (A · Btᵀ + bias) * alpha ----------------
// N = K = 1024. Block tile 128x128, K-step 32, 2-stage cp.async pipeline.
#define MODE_PLAIN  0
#define MODE_QSPLIT 1
#define MODE_KV     2

struct GemmJob {
    const float* A; const float* Bt; float* C; const float* bias;
    int M; int mode; int S; int off; float alpha;
};
struct GemmBatch { GemmJob j[6]; };

#define GSTG (128 * 36)          // floats per operand per stage
#define GEMM_SMEM (4 * GSTG * 4) // 2 stages x (A+B) = 73728 bytes

__global__ __launch_bounds__(256, 2) void gemm_tf32_multi(GemmBatch batch)
{
    extern __shared__ float smem[];
    const GemmJob jb = batch.j[blockIdx.z];
    const int bm = blockIdx.y * 128;
    if (bm >= jb.M) return;
    const int bn = blockIdx.x * 128;

    const int tid  = threadIdx.x;
    const int w    = tid >> 5;
    const int lane = tid & 31;
    const int gid  = lane >> 2;
    const int ctid = lane & 3;
    const int wm = (w & 1) * 64;
    const int wn = (w >> 1) * 32;
    const int lr = tid >> 3;
    const int lc = (tid & 7) * 4;

    const float* A  = jb.A;
    const float* Bt = jb.Bt;

    // issue one K-tile (32 wide) into stage s
    auto issue = [&](int k0, int s) {
        float* as = smem + s * 2 * GSTG;
        float* bs = as + GSTG;
        #pragma unroll
        for (int p = 0; p < 4; p++) {
            cp16(s2u(&as[(lr + p * 32) * 36 + lc]), &A [(long long)(bm + lr + p * 32) * DHID + k0 + lc]);
            cp16(s2u(&bs[(lr + p * 32) * 36 + lc]), &Bt[(long long)(bn + lr + p * 32) * DHID + k0 + lc]);
        }
        cp_commit();
    };

    float acc[4][4][4];
    #pragma unroll
    for (int i = 0; i < 4; i++)
        #pragma unroll
        for (int j = 0; j < 4; j++)
            #pragma unroll
            for (int e = 0; e < 4; e++) acc[i][j][e] = 0.0f;

    issue(0, 0);

    for (int it = 0; it < 32; it++) {
        cp_wait0();
        __syncthreads();
        if (it + 1 < 32) issue((it + 1) * 32, (it + 1) & 1);

        const float* as = smem + (it & 1) * 2 * GSTG;
        const float* bs = as + GSTG;

        #pragma unroll
        for (int ks = 0; ks < 4; ks++) {
            const int kk = ks * 8;
            uint32_t af[4][4], bf[4][2];
            #pragma unroll
            for (int mf = 0; mf < 4; mf++) {
                const int r = wm + mf * 16 + gid;
                af[mf][0] = f2tf(as[r       * 36 + kk + ctid]);
                af[mf][1] = f2tf(as[(r + 8) * 36 + kk + ctid]);
                af[mf][2] = f2tf(as[r       * 36 + kk + ctid + 4]);
                af[mf][3] = f2tf(as[(r + 8) * 36 + kk + ctid + 4]);
            }
            #pragma unroll
            for (int nf = 0; nf < 4; nf++) {
                const int c = wn + nf * 8 + gid;
                bf[nf][0] = f2tf(bs[c * 36 + kk + ctid]);
                bf[nf][1] = f2tf(bs[c * 36 + kk + ctid + 4]);
            }
            #pragma unroll
            for (int mf = 0; mf < 4; mf++)
                #pragma unroll
                for (int nf = 0; nf < 4; nf++)
                    mma_tf32(acc[mf][nf], af[mf], bf[nf]);
        }
    }

    // epilogue
    #pragma unroll
    for (int mf = 0; mf < 4; mf++) {
        #pragma unroll
        for (int nf = 0; nf < 4; nf++) {
            const int r0 = bm + wm + mf * 16 + gid;
            const int c0 = bn + wn + nf * 8 + 2 * ctid;
            const float b0 = jb.bias ? jb.bias[c0]     : 0.0f;
            const float b1 = jb.bias ? jb.bias[c0 + 1] : 0.0f;
            float2 v0, v1;
            v0.x = (acc[mf][nf][0] + b0) * jb.alpha;
            v0.y = (acc[mf][nf][1] + b1) * jb.alpha;
            v1.x = (acc[mf][nf][2] + b0) * jb.alpha;
            v1.y = (acc[mf][nf][3] + b1) * jb.alpha;
            long long i0, i1;
            if (jb.mode == MODE_PLAIN) {
                i0 = (long long)r0 * DHID + c0;
                i1 = (long long)(r0 + 8) * DHID + c0;
            } else {
                const int h  = c0 >> 6, hd = c0 & 63;
                const int b_  = r0 / jb.S, s0 = r0 - b_ * jb.S;
                const int b_2 = (r0 + 8) / jb.S, s1 = (r0 + 8) - b_2 * jb.S;
                if (jb.mode == MODE_QSPLIT) {
                    i0 = (((long long)(b_  * NHEAD + h)) * jb.S + s0) * HDIM + hd;
                    i1 = (((long long)(b_2 * NHEAD + h)) * jb.S + s1) * HDIM + hd;
                } else { // MODE_KV
                    i0 = (((long long)(b_  * NHEAD + h)) * SKV + jb.off + s0) * HDIM + hd;
                    i1 = (((long long)(b_2 * NHEAD + h)) * SKV + jb.off + s1) * HDIM + hd;
                }
            }
            *reinterpret_cast<float2*>(&jb.C[i0]) = v0;
            *reinterpret_cast<float2*>(&jb.C[i1]) = v1;
        }
    }
}

// ---------------- fused attention (text+image merged) ----------------
// Block: 32 q-rows of one (b,h). Full 1088-wide score row in smem.
// K/V streamed in 64-row chunks through a 2-stage cp.async buffer.
#define NCHUNK (SKV / 64)   // 17
#define ATTN_SMEM ((32 * SC_STRIDE + 32 * Q_STRIDE + 2 * 64 * KV_STRIDE) * 4)

__global__ __launch_bounds__(256, 1) void attn_kernel(
    const float* __restrict__ Qt, const float* __restrict__ Qi,
    const float* __restrict__ Kg, const float* __restrict__ Vg,
    float* __restrict__ Wt, float* __restrict__ Wi,
    float* __restrict__ Ot, float* __restrict__ Oi)
{
    extern __shared__ char sm[];
    float* Sc = reinterpret_cast<float*>(sm);                       // 32 x SC_STRIDE
    float* Qs = Sc + 32 * SC_STRIDE;                                // 32 x Q_STRIDE
    float* KV = Qs + 32 * Q_STRIDE;                                 // 2 x 64 x KV_STRIDE

    const bool isT = blockIdx.x < (ST / 32);
    const int  Sq  = isT ? ST : SI;
    const float* Q   = isT ? Qt : Qi;
    float* Wout      = isT ? Wt : Wi;
    float* O         = isT ? Ot : Oi;
    const int qbase  = (isT ? blockIdx.x : blockIdx.x - ST / 32) * 32;

    const int z = blockIdx.y;
    const int b = z >> 4, h = z & 15;
    const int tid  = threadIdx.x;
    const int w    = tid >> 5;
    const int lane = tid & 31;
    const int gid  = lane >> 2;
    const int ctid = lane & 3;

    auto issueK = [&](int c, int s) {
        float* dst = KV + s * 64 * KV_STRIDE;
        #pragma unroll
        for (int i = tid; i < 64 * 16; i += 256) {
            const int r = i >> 4, c4 = (i & 15) * 4;
            cp16(s2u(&dst[r * KV_STRIDE + c4]), &Kg[((long long)z * SKV + c * 64 + r) * HDIM + c4]);
        }
        cp_commit();
    };
    auto issueV = [&](int c, int s) {
        float* dst = KV + s * 64 * KV_STRIDE;
        #pragma unroll
        for (int i = tid; i < 64 * 16; i += 256) {
            const int r = i >> 4, c4 = (i & 15) * 4;
            cp16(s2u(&dst[r * KV_STRIDE + c4]), &Vg[((long long)z * SKV + c * 64 + r) * HDIM + c4]);
        }
        cp_commit();
    };

    // Q staging + K chunk 0
    for (int i = tid; i < 32 * 16; i += 256) {
        const int r = i >> 4, c4 = (i & 15) * 4;
        cp16(s2u(&Qs[r * Q_STRIDE + c4]), &Q[((long long)z * Sq + qbase + r) * HDIM + c4]);
    }
    cp_commit();
    issueK(0, 0);
    cp_wait0();
    __syncthreads();

    // hoist Q fragments (tf32) into registers for all 8 k-steps
    uint32_t qf[8][2][4];
    #pragma unroll
    for (int ks = 0; ks < 8; ks++) {
        const int kk = ks * 8;
        #pragma unroll
        for (int mf = 0; mf < 2; mf++) {
            const int r = mf * 16 + gid;
            qf[ks][mf][0] = f2tf(Qs[r       * Q_STRIDE + kk + ctid]);
            qf[ks][mf][1] = f2tf(Qs[(r + 8) * Q_STRIDE + kk + ctid]);
            qf[ks][mf][2] = f2tf(Qs[r       * Q_STRIDE + kk + ctid + 4]);
            qf[ks][mf][3] = f2tf(Qs[(r + 8) * Q_STRIDE + kk + ctid + 4]);
        }
    }

    // ---- phase 1: scores ----
    for (int c = 0; c < NCHUNK; c++) {
        if (c > 0) { cp_wait0(); __syncthreads(); }
        if (c + 1 < NCHUNK) issueK(c + 1, (c + 1) & 1);

        const float* buf = KV + (c & 1) * 64 * KV_STRIDE;
        float acc[2][4];
        #pragma unroll
        for (int mf = 0; mf < 2; mf++)
            #pragma unroll
            for (int e = 0; e < 4; e++) acc[mf][e] = 0.0f;

        const int col = w * 8 + gid;
        #pragma unroll
        for (int ks = 0; ks < 8; ks++) {
            const int kk = ks * 8;
            uint32_t bf[2];
            bf[0] = f2tf(buf[col * KV_STRIDE + kk + ctid]);
            bf[1] = f2tf(buf[col * KV_STRIDE + kk + ctid + 4]);
            mma_tf32(acc[0], qf[ks][0], bf);
            mma_tf32(acc[1], qf[ks][1], bf);
        }
        const int c0 = c * 64 + w * 8 + 2 * ctid;
        *reinterpret_cast<float2*>(&Sc[gid        * SC_STRIDE + c0]) = make_float2(acc[0][0], acc[0][1]);
        *reinterpret_cast<float2*>(&Sc[(gid + 8)  * SC_STRIDE + c0]) = make_float2(acc[0][2], acc[0][3]);
        *reinterpret_cast<float2*>(&Sc[(gid + 16) * SC_STRIDE + c0]) = make_float2(acc[1][0], acc[1][1]);
        *reinterpret_cast<float2*>(&Sc[(gid + 24) * SC_STRIDE + c0]) = make_float2(acc[1][2], acc[1][3]);

        __syncthreads();  // chunk done; safe to rewrite buffers next iter / phase boundary
    }

    // KV buffers free: start V chunk 0 now, overlap with softmax
    issueV(0, 0);

    // ---- phase 2: softmax + w write + in-place tf32 convert ----
    {
        const int r = tid >> 3, l8 = tid & 7;
        float mx = -1e30f;
        for (int i = l8; i < SKV; i += 8) mx = fmaxf(mx, Sc[r * SC_STRIDE + i]);
        #pragma unroll
        for (int o = 4; o > 0; o >>= 1) mx = fmaxf(mx, __shfl_xor_sync(0xffffffffu, mx, o));
        float sum = 0.0f;
        for (int i = l8; i < SKV; i += 8) {
            float e = __expf(Sc[r * SC_STRIDE + i] - mx);
            Sc[r * SC_STRIDE + i] = e;
            sum += e;
        }
        #pragma unroll
        for (int o = 4; o > 0; o >>= 1) sum += __shfl_xor_sync(0xffffffffu, sum, o);
        const float inv = 1.0f / sum;
        float* wrow = Wout + ((long long)z * Sq + qbase + r) * SKV;
        uint32_t* Scu = reinterpret_cast<uint32_t*>(Sc);
        for (int i = l8; i < SKV; i += 8) {
            const float v = Sc[r * SC_STRIDE + i] * inv;
            wrow[i] = v;
            Scu[r * SC_STRIDE + i] = f2tf(v);
        }
    }

    // ---- phase 3: O = w · V ----
    const uint32_t* Scu = reinterpret_cast<const uint32_t*>(Sc);
    float oacc[2][4];
    #pragma unroll
    for (int mf = 0; mf < 2; mf++)
        #pragma unroll
        for (int e = 0; e < 4; e++) oacc[mf][e] = 0.0f;
    const int wn3 = w * 8;

    for (int c = 0; c < NCHUNK; c++) {
        cp_wait0();
        __syncthreads();
        if (c + 1 < NCHUNK) issueV(c + 1, (c + 1) & 1);

        const float* buf = KV + (c & 1) * 64 * KV_STRIDE;
        const int cb = c * 64;
        #pragma unroll
        for (int ks = 0; ks < 8; ks++) {
            const int kk = ks * 8;
            uint32_t af[2][4], bf[2];
            #pragma unroll
            for (int mf = 0; mf < 2; mf++) {
                const int r = mf * 16 + gid;
                af[mf][0] = Scu[r       * SC_STRIDE + cb + kk + ctid];
                af[mf][1] = Scu[(r + 8) * SC_STRIDE + cb + kk + ctid];
                af[mf][2] = Scu[r       * SC_STRIDE + cb + kk + ctid + 4];
                af[mf][3] = Scu[(r + 8) * SC_STRIDE + cb + kk + ctid + 4];
            }
            bf[0] = f2tf(buf[(kk + ctid)     * KV_STRIDE + wn3 + gid]);
            bf[1] = f2tf(buf[(kk + ctid + 4) * KV_STRIDE + wn3 + gid]);
            mma_tf32(oacc[0], af[0], bf);
            mma_tf32(oacc[1], af[1], bf);
        }
        __syncthreads();  // all warps done with this buffer before it is refilled
    }

    // epilogue: head-merged O
    #pragma unroll
    for (int mf = 0; mf < 2; mf++) {
        const int r0 = qbase + mf * 16 + gid;
        const int c0 = h * HDIM + wn3 + 2 * ctid;
        *reinterpret_cast<float2*>(&O[((long long)b * Sq + r0) * DHID + c0])     = make_float2(oacc[mf][0], oacc[mf][1]);
        *reinterpret_cast<float2*>(&O[((long long)b * Sq + r0 + 8) * DHID + c0]) = make_float2(oacc[mf][2], oacc[mf][3]);
    }
}

// ---------------- host orchestration ----------------
extern "C" void kernel_launch(void* const* d_in, const int* in_sizes, int n_in,
                              void* d_out, int out_size)
{
    const float* q_text  = (const float*)d_in[0];
    const float* q_image = (const float*)d_in[1];
    const float* k_text  = (const float*)d_in[2];
    const float* k_image = (const float*)d_in[3];
    const float* Wq_t = (const float*)d_in[4];  const float* bq_t = (const float*)d_in[5];
    const float* Wk_t = (const float*)d_in[6];  const float* bk_t = (const float*)d_in[7];
    const float* Wv_t = (const float*)d_in[8];  const float* bv_t = (const float*)d_in[9];
    const float* Wq_i = (const float*)d_in[10]; const float* bq_i = (const float*)d_in[11];
    const float* Wk_i = (const float*)d_in[12]; const float* bk_i = (const float*)d_in[13];
    const float* Wv_i = (const float*)d_in[14]; const float* bv_i = (const float*)d_in[15];
    const float* lng_t = (const float*)d_in[16]; const float* lnb_t = (const float*)d_in[17];
    const float* lng_i = (const float*)d_in[18]; const float* lnb_i = (const float*)d_in[19];
    const float* Wo = (const float*)d_in[20]; const float* bo = (const float*)d_in[21];

    float* out = (float*)d_out;
    const long long OUT_T = 0;
    const long long OUT_I = (long long)BATCH * ST * DHID;
    const long long W_T   = OUT_I + (long long)BATCH * SI * DHID;
    const long long W_I   = W_T + (long long)BATCH * NHEAD * ST * SKV;

    float *pLNQT, *pLNQI, *pLNKT, *pLNKI, *pQT, *pQI, *pK, *pV, *pOT, *pOI;
    cudaGetSymbolAddress((void**)&pLNQT, g_ln_qt);
    cudaGetSymbolAddress((void**)&pLNQI, g_ln_qi);
    cudaGetSymbolAddress((void**)&pLNKT, g_ln_kt);
    cudaGetSymbolAddress((void**)&pLNKI, g_ln_ki);
    cudaGetSymbolAddress((void**)&pQT,   g_Q_t);
    cudaGetSymbolAddress((void**)&pQI,   g_Q_i);
    cudaGetSymbolAddress((void**)&pK,    g_K);
    cudaGetSymbolAddress((void**)&pV,    g_V);
    cudaGetSymbolAddress((void**)&pOT,   g_O_t);
    cudaGetSymbolAddress((void**)&pOI,   g_O_i);

    cudaFuncSetAttribute(gemm_tf32_multi, cudaFuncAttributeMaxDynamicSharedMemorySize, GEMM_SMEM);
    cudaFuncSetAttribute(attn_kernel,     cudaFuncAttributeMaxDynamicSharedMemorySize, ATTN_SMEM);

    // 1) LayerNorms (one launch, 4 jobs)
    {
        LnBatch lb;
        lb.j[0] = { q_text,  lng_t, lnb_t, pLNQT, BATCH * ST };
        lb.j[1] = { q_image, lng_i, lnb_i, pLNQI, BATCH * SI };
        lb.j[2] = { k_text,  lng_t, lnb_t, pLNKT, BATCH * ST };
        lb.j[3] = { k_image, lng_i, lnb_i, pLNKI, BATCH * SI };
        ln_multi<<<dim3(BATCH * SI, 4), 256>>>(lb);
    }

    // 2) Projections (one launch, 6 jobs)
    {
        GemmBatch gb;
        gb.j[0] = { pLNQT, Wq_t, pQT, bq_t, BATCH * ST, MODE_QSPLIT, ST, 0,  QSCALE };
        gb.j[1] = { pLNQI, Wq_i, pQI, bq_i, BATCH * SI, MODE_QSPLIT, SI, 0,  QSCALE };
        gb.j[2] = { pLNKT, Wk_t, pK,  bk_t, BATCH * ST, MODE_KV,     ST, 0,  1.0f };
        gb.j[3] = { pLNKI, Wk_i, pK,  bk_i, BATCH * SI, MODE_KV,     SI, ST, 1.0f };
        gb.j[4] = { pLNKT, Wv_t, pV,  bv_t, BATCH * ST, MODE_KV,     ST, 0,  1.0f };
        gb.j[5] = { pLNKI, Wv_i, pV,  bv_i, BATCH * SI, MODE_KV,     SI, ST, 1.0f };
        gemm_tf32_multi<<<dim3(DHID / 128, (BATCH * SI) / 128, 6), 256, GEMM_SMEM>>>(gb);
    }

    // 3) Fused attention (text + image in one launch)
    attn_kernel<<<dim3(ST / 32 + SI / 32, BATCH * NHEAD), 256, ATTN_SMEM>>>(
        pQT, pQI, pK, pV, out + W_T, out + W_I, pOT, pOI);

    // 4) Output projection (one launch, 2 jobs)
    {
        GemmBatch gb;
        gb.j[0] = { pOT, Wo, out + OUT_T, bo, BATCH * ST, MODE_PLAIN, 0, 0, 1.0f };
        gb.j[1] = { pOI, Wo, out + OUT_I, bo, BATCH * SI, MODE_PLAIN, 0, 0, 1.0f };
        gb.j[2] = gb.j[1]; gb.j[3] = gb.j[1]; gb.j[4] = gb.j[1]; gb.j[5] = gb.j[1];
        gemm_tf32_multi<<<dim3(DHID / 128, (BATCH * SI) / 128, 2), 256, GEMM_SMEM>>>(gb);
    }

    (void)in_sizes; (void)n_in; (void)out_size;
}

// round 8
// speedup vs baseline: 4.2241x; 1.0897x over previous
#include <cuda_runtime.h>
#include <cstdint>

#define DHID  1024
#define NHEAD 16
#define HDIM  64
#define BATCH 4
#define ST    512
#define SI    576
#define SKV   1088
#define QSCALE 0.125f
#define LN_EPS 1e-5f

#define SC_STRIDE 1092   // scores row stride (floats), %32==4
#define Q_STRIDE  68     // Q staging stride, %32==4
#define KV_STRIDE 72     // K/V chunk stride, %32==8

// ---------------- scratch (device globals; allocation-free) ----------------
__device__ float g_ln_qt[BATCH * ST * DHID];
__device__ float g_ln_qi[BATCH * SI * DHID];
__device__ float g_ln_kt[BATCH * ST * DHID];
__device__ float g_ln_ki[BATCH * SI * DHID];
__device__ float g_Q_t[BATCH * NHEAD * ST * HDIM];
__device__ float g_Q_i[BATCH * NHEAD * SI * HDIM];
__device__ float g_K  [BATCH * NHEAD * SKV * HDIM];
__device__ float g_V  [BATCH * NHEAD * SKV * HDIM];
__device__ float g_O_t[BATCH * ST * DHID];
__device__ float g_O_i[BATCH * SI * DHID];

// ---------------- helpers ----------------
__device__ __forceinline__ uint32_t f2tf(float f) {
    uint32_t u; asm("cvt.rna.tf32.f32 %0, %1;" : "=r"(u) : "f"(f)); return u;
}
__device__ __forceinline__ void mma_tf32(float* d, const uint32_t* a, const uint32_t* b) {
    asm volatile("mma.sync.aligned.m16n8k8.row.col.f32.tf32.tf32.f32 "
                 "{%0,%1,%2,%3}, {%4,%5,%6,%7}, {%8,%9}, {%0,%1,%2,%3};"
                 : "+f"(d[0]), "+f"(d[1]), "+f"(d[2]), "+f"(d[3])
                 : "r"(a[0]), "r"(a[1]), "r"(a[2]), "r"(a[3]), "r"(b[0]), "r"(b[1]));
}
__device__ __forceinline__ uint32_t s2u(const void* p) {
    return (uint32_t)__cvta_generic_to_shared(p);
}
__device__ __forceinline__ void cp16(uint32_t dst, const void* src) {
    asm volatile("cp.async.cg.shared.global [%0], [%1], 16;" :: "r"(dst), "l"(src));
}
__device__ __forceinline__ void cp_commit() {
    asm volatile("cp.async.commit_group;");
}
__device__ __forceinline__ void cp_wait0() {
    asm volatile("cp.async.wait_group 0;" ::: "memory");
}
__device__ __forceinline__ void cp_wait1() {
    asm volatile("cp.async.wait_group 1;" ::: "memory");
}

// ---------------- LayerNorm (4 jobs in one launch) ----------------
struct LnJob { const float* x; const float* g; const float* b; float* y; int rows; };
struct LnBatch { LnJob j[4]; };

__global__ __launch_bounds__(256) void ln_multi(LnBatch batch)
{
    const LnJob jb = batch.j[blockIdx.y];
    const int row = blockIdx.x;
    if (row >= jb.rows) return;
    const int t = threadIdx.x;
    const float4 xv = reinterpret_cast<const float4*>(jb.x + (long long)row * DHID)[t];

    float s  = xv.x + xv.y + xv.z + xv.w;
    float sq = xv.x * xv.x + xv.y * xv.y + xv.z * xv.z + xv.w * xv.w;

    __shared__ float red_s[8], red_q[8];
    #pragma unroll
    for (int o = 16; o > 0; o >>= 1) {
        s  += __shfl_xor_sync(0xffffffffu, s,  o);
        sq += __shfl_xor_sync(0xffffffffu, sq, o);
    }
    if ((t & 31) == 0) { red_s[t >> 5] = s; red_q[t >> 5] = sq; }
    __syncthreads();
    float ts = red_s[t & 7], tq = red_q[t & 7];
    #pragma unroll
    for (int o = 4; o > 0; o >>= 1) {
        ts += __shfl_xor_sync(0xffffffffu, ts, o);
        tq += __shfl_xor_sync(0xffffffffu, tq, o);
    }
    ts = __shfl_sync(0xffffffffu, ts, 0);
    tq = __shfl_sync(0xffffffffu, tq, 0);

    const float mean = ts * (1.0f / DHID);
    const float rstd = rsqrtf(tq * (1.0f / DHID) - mean * mean + LN_EPS);

    const float4 gv = reinterpret_cast<const float4*>(jb.g)[t];
    const float4 bv = reinterpret_cast<const float4*>(jb.b)[t];
    float4 o;
    o.x = (xv.x - mean) * rstd * gv.x + bv.x;
    o.y = (xv.y - mean) * rstd * gv.y + bv.y;
    o.z = (xv.z - mean) * rstd * gv.z + bv.z;
    o.w = (xv.w - mean) * rstd * gv.w + bv.w;
    reinterpret_cast<float4*>(jb.y + (long long)row * DHID)[t] = o;
}

// ---------------- batched tf32 GEMM ----------------
#define MODE_PLAIN  0
#define MODE_QSPLIT 1
#define MODE_KV     2

struct GemmJob {
    const float* A; const float* Bt; float* C; const float* bias;
    int M; int mode; int S; int off; float alpha;
};
struct GemmBatch { GemmJob j[6]; };

#define GSTG (128 * 36)
#define GEMM_SMEM (4 * GSTG * 4)

__global__ __launch_bounds__(256, 2) void gemm_tf32_multi(GemmBatch batch)
{
    extern __shared__ float smem[];
    const GemmJob jb = batch.j[blockIdx.z];
    const int bm = blockIdx.y * 128;
    if (bm >= jb.M) return;
    const int bn = blockIdx.x * 128;

    const int tid  = threadIdx.x;
    const int w    = tid >> 5;
    const int lane = tid & 31;
    const int gid  = lane >> 2;
    const int ctid = lane & 3;
    const int wm = (w & 1) * 64;
    const int wn = (w >> 1) * 32;
    const int lr = tid >> 3;
    const int lc = (tid & 7) * 4;

    const float* A  = jb.A;
    const float* Bt = jb.Bt;

    auto issue = [&](int k0, int s) {
        float* as = smem + s * 2 * GSTG;
        float* bs = as + GSTG;
        #pragma unroll
        for (int p = 0; p < 4; p++) {
            cp16(s2u(&as[(lr + p * 32) * 36 + lc]), &A [(long long)(bm + lr + p * 32) * DHID + k0 + lc]);
            cp16(s2u(&bs[(lr + p * 32) * 36 + lc]), &Bt[(long long)(bn + lr + p * 32) * DHID + k0 + lc]);
        }
        cp_commit();
    };

    float acc[4][4][4];
    #pragma unroll
    for (int i = 0; i < 4; i++)
        #pragma unroll
        for (int j = 0; j < 4; j++)
            #pragma unroll
            for (int e = 0; e < 4; e++) acc[i][j][e] = 0.0f;

    issue(0, 0);

    for (int it = 0; it < 32; it++) {
        cp_wait0();
        __syncthreads();
        if (it + 1 < 32) issue((it + 1) * 32, (it + 1) & 1);

        const float* as = smem + (it & 1) * 2 * GSTG;
        const float* bs = as + GSTG;

        #pragma unroll
        for (int ks = 0; ks < 4; ks++) {
            const int kk = ks * 8;
            uint32_t af[4][4], bf[4][2];
            #pragma unroll
            for (int mf = 0; mf < 4; mf++) {
                const int r = wm + mf * 16 + gid;
                af[mf][0] = f2tf(as[r       * 36 + kk + ctid]);
                af[mf][1] = f2tf(as[(r + 8) * 36 + kk + ctid]);
                af[mf][2] = f2tf(as[r       * 36 + kk + ctid + 4]);
                af[mf][3] = f2tf(as[(r + 8) * 36 + kk + ctid + 4]);
            }
            #pragma unroll
            for (int nf = 0; nf < 4; nf++) {
                const int c = wn + nf * 8 + gid;
                bf[nf][0] = f2tf(bs[c * 36 + kk + ctid]);
                bf[nf][1] = f2tf(bs[c * 36 + kk + ctid + 4]);
            }
            #pragma unroll
            for (int mf = 0; mf < 4; mf++)
                #pragma unroll
                for (int nf = 0; nf < 4; nf++)
                    mma_tf32(acc[mf][nf], af[mf], bf[nf]);
        }
    }

    #pragma unroll
    for (int mf = 0; mf < 4; mf++) {
        #pragma unroll
        for (int nf = 0; nf < 4; nf++) {
            const int r0 = bm + wm + mf * 16 + gid;
            const int c0 = bn + wn + nf * 8 + 2 * ctid;
            const float b0 = jb.bias ? jb.bias[c0]     : 0.0f;
            const float b1 = jb.bias ? jb.bias[c0 + 1] : 0.0f;
            float2 v0, v1;
            v0.x = (acc[mf][nf][0] + b0) * jb.alpha;
            v0.y = (acc[mf][nf][1] + b1) * jb.alpha;
            v1.x = (acc[mf][nf][2] + b0) * jb.alpha;
            v1.y = (acc[mf][nf][3] + b1) * jb.alpha;
            long long i0, i1;
            if (jb.mode == MODE_PLAIN) {
                i0 = (long long)r0 * DHID + c0;
                i1 = (long long)(r0 + 8) * DHID + c0;
            } else {
                const int h  = c0 >> 6, hd = c0 & 63;
                const int b_  = r0 / jb.S, s0 = r0 - b_ * jb.S;
                const int b_2 = (r0 + 8) / jb.S, s1 = (r0 + 8) - b_2 * jb.S;
                if (jb.mode == MODE_QSPLIT) {
                    i0 = (((long long)(b_  * NHEAD + h)) * jb.S + s0) * HDIM + hd;
                    i1 = (((long long)(b_2 * NHEAD + h)) * jb.S + s1) * HDIM + hd;
                } else {
                    i0 = (((long long)(b_  * NHEAD + h)) * SKV + jb.off + s0) * HDIM + hd;
                    i1 = (((long long)(b_2 * NHEAD + h)) * SKV + jb.off + s1) * HDIM + hd;
                }
            }
            *reinterpret_cast<float2*>(&jb.C[i0]) = v0;
            *reinterpret_cast<float2*>(&jb.C[i1]) = v1;
        }
    }
}

// ---------------- fused attention (512 threads, 3-stage cp.async) ----------------
#define NCHUNK (SKV / 64)   // 17
#define ATTN_SMEM ((32 * SC_STRIDE + 32 * Q_STRIDE + 3 * 64 * KV_STRIDE) * 4)

__global__ __launch_bounds__(512, 1) void attn_kernel(
    const float* __restrict__ Qt, const float* __restrict__ Qi,
    const float* __restrict__ Kg, const float* __restrict__ Vg,
    float* __restrict__ Wt, float* __restrict__ Wi,
    float* __restrict__ Ot, float* __restrict__ Oi)
{
    extern __shared__ char sm[];
    float* Sc = reinterpret_cast<float*>(sm);       // 32 x SC_STRIDE
    float* Qs = Sc + 32 * SC_STRIDE;                // 32 x Q_STRIDE
    float* KV = Qs + 32 * Q_STRIDE;                 // 3 x 64 x KV_STRIDE

    const bool isT = blockIdx.x < (ST / 32);
    const int  Sq  = isT ? ST : SI;
    const float* Q   = isT ? Qt : Qi;
    float* Wout      = isT ? Wt : Wi;
    float* O         = isT ? Ot : Oi;
    const int qbase  = (isT ? blockIdx.x : blockIdx.x - ST / 32) * 32;

    const int z = blockIdx.y;
    const int b = z >> 4, h = z & 15;
    const int tid  = threadIdx.x;
    const int w    = tid >> 5;
    const int lane = tid & 31;
    const int gid  = lane >> 2;
    const int ctid = lane & 3;
    const int mhalf  = w >> 3;          // 0/1 -> rows [0,16) / [16,32)
    const int nstrip = (w & 7) * 8;     // 8-col strip

    auto issueK = [&](int c, int s) {
        float* dst = KV + s * 64 * KV_STRIDE;
        #pragma unroll
        for (int i = tid; i < 64 * 16; i += 512) {
            const int r = i >> 4, c4 = (i & 15) * 4;
            cp16(s2u(&dst[r * KV_STRIDE + c4]), &Kg[((long long)z * SKV + c * 64 + r) * HDIM + c4]);
        }
        cp_commit();
    };
    auto issueV = [&](int c, int s) {
        float* dst = KV + s * 64 * KV_STRIDE;
        #pragma unroll
        for (int i = tid; i < 64 * 16; i += 512) {
            const int r = i >> 4, c4 = (i & 15) * 4;
            cp16(s2u(&dst[r * KV_STRIDE + c4]), &Vg[((long long)z * SKV + c * 64 + r) * HDIM + c4]);
        }
        cp_commit();
    };

    // group 0: Q + K chunk 0 ; group 1: K chunk 1
    for (int i = tid; i < 32 * 16; i += 512) {
        const int r = i >> 4, c4 = (i & 15) * 4;
        cp16(s2u(&Qs[r * Q_STRIDE + c4]), &Q[((long long)z * Sq + qbase + r) * HDIM + c4]);
    }
    issueK(0, 0);           // commits {Q, K0}
    issueK(1, 1);
    cp_wait1();             // {Q,K0} done, K1 in flight
    __syncthreads();

    // hoist this warp's Q fragments (one m-frag per warp)
    uint32_t qf[8][4];
    #pragma unroll
    for (int ks = 0; ks < 8; ks++) {
        const int kk = ks * 8;
        const int r = mhalf * 16 + gid;
        qf[ks][0] = f2tf(Qs[r       * Q_STRIDE + kk + ctid]);
        qf[ks][1] = f2tf(Qs[(r + 8) * Q_STRIDE + kk + ctid]);
        qf[ks][2] = f2tf(Qs[r       * Q_STRIDE + kk + ctid + 4]);
        qf[ks][3] = f2tf(Qs[(r + 8) * Q_STRIDE + kk + ctid + 4]);
    }

    // ---- phase 1: scores ----
    for (int c = 0; c < NCHUNK; c++) {
        if (c > 0) {
            // tail-aware wait: mid-stream one group may stay in flight, but the
            // LAST chunk has no successor issue, so it must drain completely.
            if (c == NCHUNK - 1) cp_wait0(); else cp_wait1();
            __syncthreads();
        }
        if (c + 2 < NCHUNK) issueK(c + 2, (c + 2) % 3);

        const float* buf = KV + (c % 3) * 64 * KV_STRIDE;
        float acc[4] = {0.0f, 0.0f, 0.0f, 0.0f};
        const int col = nstrip + gid;
        #pragma unroll
        for (int ks = 0; ks < 8; ks++) {
            const int kk = ks * 8;
            uint32_t bf[2];
            bf[0] = f2tf(buf[col * KV_STRIDE + kk + ctid]);
            bf[1] = f2tf(buf[col * KV_STRIDE + kk + ctid + 4]);
            mma_tf32(acc, qf[ks], bf);
        }
        const int r0 = mhalf * 16 + gid;
        const int c0 = c * 64 + nstrip + 2 * ctid;
        *reinterpret_cast<float2*>(&Sc[r0 * SC_STRIDE + c0])       = make_float2(acc[0], acc[1]);
        *reinterpret_cast<float2*>(&Sc[(r0 + 8) * SC_STRIDE + c0]) = make_float2(acc[2], acc[3]);
    }
    __syncthreads();   // all scores in smem; all K-stage compute done

    // V chunks 0,1 overlap the softmax
    issueV(0, 0);
    issueV(1, 1);

    // ---- phase 2: softmax + w write + in-place tf32 convert ----
    {
        const int r = tid >> 4, l = tid & 15;   // 16 threads per row
        float mx = -1e30f;
        for (int i = l; i < SKV; i += 16) mx = fmaxf(mx, Sc[r * SC_STRIDE + i]);
        #pragma unroll
        for (int o = 8; o > 0; o >>= 1) mx = fmaxf(mx, __shfl_xor_sync(0xffffffffu, mx, o));
        float sum = 0.0f;
        for (int i = l; i < SKV; i += 16) {
            float e = __expf(Sc[r * SC_STRIDE + i] - mx);
            Sc[r * SC_STRIDE + i] = e;
            sum += e;
        }
        #pragma unroll
        for (int o = 8; o > 0; o >>= 1) sum += __shfl_xor_sync(0xffffffffu, sum, o);
        const float inv = 1.0f / sum;
        float* wrow = Wout + ((long long)z * Sq + qbase + r) * SKV;
        uint32_t* Scu = reinterpret_cast<uint32_t*>(Sc);
        for (int i = l; i < SKV; i += 16) {
            const float v = Sc[r * SC_STRIDE + i] * inv;
            wrow[i] = v;
            Scu[r * SC_STRIDE + i] = f2tf(v);
        }
    }

    // ---- phase 3: O = w · V ----
    const uint32_t* Scu = reinterpret_cast<const uint32_t*>(Sc);
    float oacc[4] = {0.0f, 0.0f, 0.0f, 0.0f};

    for (int c = 0; c < NCHUNK; c++) {
        if (c == NCHUNK - 1) cp_wait0(); else cp_wait1();   // tail-aware drain
        __syncthreads();   // V chunk c ready; softmax fully visible (c==0); stage reuse safe
        if (c + 2 < NCHUNK) issueV(c + 2, (c + 2) % 3);

        const float* buf = KV + (c % 3) * 64 * KV_STRIDE;
        const int cb = c * 64;
        #pragma unroll
        for (int ks = 0; ks < 8; ks++) {
            const int kk = ks * 8;
            uint32_t af[4], bf[2];
            const int r = mhalf * 16 + gid;
            af[0] = Scu[r       * SC_STRIDE + cb + kk + ctid];
            af[1] = Scu[(r + 8) * SC_STRIDE + cb + kk + ctid];
            af[2] = Scu[r       * SC_STRIDE + cb + kk + ctid + 4];
            af[3] = Scu[(r + 8) * SC_STRIDE + cb + kk + ctid + 4];
            bf[0] = f2tf(buf[(kk + ctid)     * KV_STRIDE + nstrip + gid]);
            bf[1] = f2tf(buf[(kk + ctid + 4) * KV_STRIDE + nstrip + gid]);
            mma_tf32(oacc, af, bf);
        }
    }

    // epilogue: head-merged O
    {
        const int r0 = qbase + mhalf * 16 + gid;
        const int c0 = h * HDIM + nstrip + 2 * ctid;
        *reinterpret_cast<float2*>(&O[((long long)b * Sq + r0) * DHID + c0])     = make_float2(oacc[0], oacc[1]);
        *reinterpret_cast<float2*>(&O[((long long)b * Sq + r0 + 8) * DHID + c0]) = make_float2(oacc[2], oacc[3]);
    }
}

// ---------------- host orchestration ----------------
extern "C" void kernel_launch(void* const* d_in, const int* in_sizes, int n_in,
                              void* d_out, int out_size)
{
    const float* q_text  = (const float*)d_in[0];
    const float* q_image = (const float*)d_in[1];
    const float* k_text  = (const float*)d_in[2];
    const float* k_image = (const float*)d_in[3];
    const float* Wq_t = (const float*)d_in[4];  const float* bq_t = (const float*)d_in[5];
    const float* Wk_t = (const float*)d_in[6];  const float* bk_t = (const float*)d_in[7];
    const float* Wv_t = (const float*)d_in[8];  const float* bv_t = (const float*)d_in[9];
    const float* Wq_i = (const float*)d_in[10]; const float* bq_i = (const float*)d_in[11];
    const float* Wk_i = (const float*)d_in[12]; const float* bk_i = (const float*)d_in[13];
    const float* Wv_i = (const float*)d_in[14]; const float* bv_i = (const float*)d_in[15];
    const float* lng_t = (const float*)d_in[16]; const float* lnb_t = (const float*)d_in[17];
    const float* lng_i = (const float*)d_in[18]; const float* lnb_i = (const float*)d_in[19];
    const float* Wo = (const float*)d_in[20]; const float* bo = (const float*)d_in[21];

    float* out = (float*)d_out;
    const long long OUT_T = 0;
    const long long OUT_I = (long long)BATCH * ST * DHID;
    const long long W_T   = OUT_I + (long long)BATCH * SI * DHID;
    const long long W_I   = W_T + (long long)BATCH * NHEAD * ST * SKV;

    float *pLNQT, *pLNQI, *pLNKT, *pLNKI, *pQT, *pQI, *pK, *pV, *pOT, *pOI;
    cudaGetSymbolAddress((void**)&pLNQT, g_ln_qt);
    cudaGetSymbolAddress((void**)&pLNQI, g_ln_qi);
    cudaGetSymbolAddress((void**)&pLNKT, g_ln_kt);
    cudaGetSymbolAddress((void**)&pLNKI, g_ln_ki);
    cudaGetSymbolAddress((void**)&pQT,   g_Q_t);
    cudaGetSymbolAddress((void**)&pQI,   g_Q_i);
    cudaGetSymbolAddress((void**)&pK,    g_K);
    cudaGetSymbolAddress((void**)&pV,    g_V);
    cudaGetSymbolAddress((void**)&pOT,   g_O_t);
    cudaGetSymbolAddress((void**)&pOI,   g_O_i);

    cudaFuncSetAttribute(gemm_tf32_multi, cudaFuncAttributeMaxDynamicSharedMemorySize, GEMM_SMEM);
    cudaFuncSetAttribute(attn_kernel,     cudaFuncAttributeMaxDynamicSharedMemorySize, ATTN_SMEM);

    // 1) LayerNorms
    {
        LnBatch lb;
        lb.j[0] = { q_text,  lng_t, lnb_t, pLNQT, BATCH * ST };
        lb.j[1] = { q_image, lng_i, lnb_i, pLNQI, BATCH * SI };
        lb.j[2] = { k_text,  lng_t, lnb_t, pLNKT, BATCH * ST };
        lb.j[3] = { k_image, lng_i, lnb_i, pLNKI, BATCH * SI };
        ln_multi<<<dim3(BATCH * SI, 4), 256>>>(lb);
    }

    // 2) Projections (one launch, 6 jobs)
    {
        GemmBatch gb;
        gb.j[0] = { pLNQT, Wq_t, pQT, bq_t, BATCH * ST, MODE_QSPLIT, ST, 0,  QSCALE };
        gb.j[1] = { pLNQI, Wq_i, pQI, bq_i, BATCH * SI, MODE_QSPLIT, SI, 0,  QSCALE };
        gb.j[2] = { pLNKT, Wk_t, pK,  bk_t, BATCH * ST, MODE_KV,     ST, 0,  1.0f };
        gb.j[3] = { pLNKI, Wk_i, pK,  bk_i, BATCH * SI, MODE_KV,     SI, ST, 1.0f };
        gb.j[4] = { pLNKT, Wv_t, pV,  bv_t, BATCH * ST, MODE_KV,     ST, 0,  1.0f };
        gb.j[5] = { pLNKI, Wv_i, pV,  bv_i, BATCH * SI, MODE_KV,     SI, ST, 1.0f };
        gemm_tf32_multi<<<dim3(DHID / 128, (BATCH * SI) / 128, 6), 256, GEMM_SMEM>>>(gb);
    }

    // 3) Fused attention
    attn_kernel<<<dim3(ST / 32 + SI / 32, BATCH * NHEAD), 512, ATTN_SMEM>>>(
        pQT, pQI, pK, pV, out + W_T, out + W_I, pOT, pOI);

    // 4) Output projection (one launch, 2 jobs)
    {
        GemmBatch gb;
        gb.j[0] = { pOT, Wo, out + OUT_T, bo, BATCH * ST, MODE_PLAIN, 0, 0, 1.0f };
        gb.j[1] = { pOI, Wo, out + OUT_I, bo, BATCH * SI, MODE_PLAIN, 0, 0, 1.0f };
        gb.j[2] = gb.j[1]; gb.j[3] = gb.j[1]; gb.j[4] = gb.j[1]; gb.j[5] = gb.j[1];
        gemm_tf32_multi<<<dim3(DHID / 128, (BATCH * SI) / 128, 2), 256, GEMM_SMEM>>>(gb);
    }

    (void)in_sizes; (void)n_in; (void)out_size;
}

// round 9
// speedup vs baseline: 4.4344x; 1.0498x over previous
#include <cuda_runtime.h>
#include <cstdint>

#define DHID  1024
#define NHEAD 16
#define HDIM  64
#define BATCH 4
#define ST    512
#define SI    576
#define SKV   1088
#define QSCALE 0.125f
#define LN_EPS 1e-5f

#define SC_STRIDE 1092   // scores row stride (floats), %32==4
#define Q_STRIDE  68     // Q staging stride, %32==4
#define KV_STRIDE 72     // K/V chunk stride, %32==8

// ---------------- scratch (device globals; allocation-free) ----------------
__device__ float g_ln_qt[BATCH * ST * DHID];
__device__ float g_ln_qi[BATCH * SI * DHID];
__device__ float g_ln_kt[BATCH * ST * DHID];
__device__ float g_ln_ki[BATCH * SI * DHID];
__device__ float g_Q_t[BATCH * NHEAD * ST * HDIM];
__device__ float g_Q_i[BATCH * NHEAD * SI * HDIM];
__device__ float g_K  [BATCH * NHEAD * SKV * HDIM];
__device__ float g_V  [BATCH * NHEAD * SKV * HDIM];
__device__ float g_O_t[BATCH * ST * DHID];
__device__ float g_O_i[BATCH * SI * DHID];
__device__ float g_Wc [7 * DHID * DHID];   // pre-rounded tf32 weights

// ---------------- helpers ----------------
__device__ __forceinline__ uint32_t f2tf(float f) {
    uint32_t u; asm("cvt.rna.tf32.f32 %0, %1;" : "=r"(u) : "f"(f)); return u;
}
__device__ __forceinline__ void mma_tf32(float* d, const uint32_t* a, const uint32_t* b) {
    asm volatile("mma.sync.aligned.m16n8k8.row.col.f32.tf32.tf32.f32 "
                 "{%0,%1,%2,%3}, {%4,%5,%6,%7}, {%8,%9}, {%0,%1,%2,%3};"
                 : "+f"(d[0]), "+f"(d[1]), "+f"(d[2]), "+f"(d[3])
                 : "r"(a[0]), "r"(a[1]), "r"(a[2]), "r"(a[3]), "r"(b[0]), "r"(b[1]));
}
__device__ __forceinline__ uint32_t s2u(const void* p) {
    return (uint32_t)__cvta_generic_to_shared(p);
}
__device__ __forceinline__ void cp16(uint32_t dst, const void* src) {
    asm volatile("cp.async.cg.shared.global [%0], [%1], 16;" :: "r"(dst), "l"(src));
}
__device__ __forceinline__ void cp_commit() {
    asm volatile("cp.async.commit_group;");
}
__device__ __forceinline__ void cp_wait0() {
    asm volatile("cp.async.wait_group 0;" ::: "memory");
}

// ---------------- tf32 pre-round for weights (7 jobs, one launch) ----------------
struct CvtJob { const float* in; float* out; };
struct CvtBatch { CvtJob j[7]; };

__global__ __launch_bounds__(256) void cvt_multi(CvtBatch batch)
{
    const CvtJob jb = batch.j[blockIdx.y];
    const int i = blockIdx.x * 256 + threadIdx.x;     // float4 index
    float4 v = reinterpret_cast<const float4*>(jb.in)[i];
    uint4 u = make_uint4(f2tf(v.x), f2tf(v.y), f2tf(v.z), f2tf(v.w));
    reinterpret_cast<uint4*>(jb.out)[i] = u;
}

// ---------------- LayerNorm (4 jobs; output pre-rounded tf32) ----------------
struct LnJob { const float* x; const float* g; const float* b; float* y; int rows; };
struct LnBatch { LnJob j[4]; };

__global__ __launch_bounds__(256) void ln_multi(LnBatch batch)
{
    const LnJob jb = batch.j[blockIdx.y];
    const int row = blockIdx.x;
    if (row >= jb.rows) return;
    const int t = threadIdx.x;
    const float4 xv = reinterpret_cast<const float4*>(jb.x + (long long)row * DHID)[t];

    float s  = xv.x + xv.y + xv.z + xv.w;
    float sq = xv.x * xv.x + xv.y * xv.y + xv.z * xv.z + xv.w * xv.w;

    __shared__ float red_s[8], red_q[8];
    #pragma unroll
    for (int o = 16; o > 0; o >>= 1) {
        s  += __shfl_xor_sync(0xffffffffu, s,  o);
        sq += __shfl_xor_sync(0xffffffffu, sq, o);
    }
    if ((t & 31) == 0) { red_s[t >> 5] = s; red_q[t >> 5] = sq; }
    __syncthreads();
    float ts = red_s[t & 7], tq = red_q[t & 7];
    #pragma unroll
    for (int o = 4; o > 0; o >>= 1) {
        ts += __shfl_xor_sync(0xffffffffu, ts, o);
        tq += __shfl_xor_sync(0xffffffffu, tq, o);
    }
    ts = __shfl_sync(0xffffffffu, ts, 0);
    tq = __shfl_sync(0xffffffffu, tq, 0);

    const float mean = ts * (1.0f / DHID);
    const float rstd = rsqrtf(tq * (1.0f / DHID) - mean * mean + LN_EPS);

    const float4 gv = reinterpret_cast<const float4*>(jb.g)[t];
    const float4 bv = reinterpret_cast<const float4*>(jb.b)[t];
    uint4 o;
    o.x = f2tf((xv.x - mean) * rstd * gv.x + bv.x);
    o.y = f2tf((xv.y - mean) * rstd * gv.y + bv.y);
    o.z = f2tf((xv.z - mean) * rstd * gv.z + bv.z);
    o.w = f2tf((xv.w - mean) * rstd * gv.w + bv.w);
    reinterpret_cast<uint4*>(jb.y + (long long)row * DHID)[t] = o;
}

// ---------------- batched tf32 GEMM (operands pre-rounded; no inner cvt) ----------------
#define MODE_PLAIN  0   // fp32 store (final outputs)
#define MODE_QSPLIT 1   // tf32-rounded store
#define MODE_KV     2   // tf32-rounded store

struct GemmJob {
    const float* A; const float* Bt; float* C; const float* bias;
    int M; int mode; int S; int off; float alpha;
};
struct GemmBatch { GemmJob j[6]; };

#define GSTG (128 * 36)
#define GEMM_SMEM (4 * GSTG * 4)

__global__ __launch_bounds__(256, 2) void gemm_tf32_multi(GemmBatch batch)
{
    extern __shared__ float smem[];
    const GemmJob jb = batch.j[blockIdx.z];
    const int bm = blockIdx.y * 128;
    if (bm >= jb.M) return;
    const int bn = blockIdx.x * 128;

    const int tid  = threadIdx.x;
    const int w    = tid >> 5;
    const int lane = tid & 31;
    const int gid  = lane >> 2;
    const int ctid = lane & 3;
    const int wm = (w & 1) * 64;
    const int wn = (w >> 1) * 32;
    const int lr = tid >> 3;
    const int lc = (tid & 7) * 4;

    const float* A  = jb.A;
    const float* Bt = jb.Bt;

    auto issue = [&](int k0, int s) {
        float* as = smem + s * 2 * GSTG;
        float* bs = as + GSTG;
        #pragma unroll
        for (int p = 0; p < 4; p++) {
            cp16(s2u(&as[(lr + p * 32) * 36 + lc]), &A [(long long)(bm + lr + p * 32) * DHID + k0 + lc]);
            cp16(s2u(&bs[(lr + p * 32) * 36 + lc]), &Bt[(long long)(bn + lr + p * 32) * DHID + k0 + lc]);
        }
        cp_commit();
    };

    float acc[4][4][4];
    #pragma unroll
    for (int i = 0; i < 4; i++)
        #pragma unroll
        for (int j = 0; j < 4; j++)
            #pragma unroll
            for (int e = 0; e < 4; e++) acc[i][j][e] = 0.0f;

    issue(0, 0);

    for (int it = 0; it < 32; it++) {
        cp_wait0();
        __syncthreads();
        if (it + 1 < 32) issue((it + 1) * 32, (it + 1) & 1);

        const uint32_t* as = reinterpret_cast<const uint32_t*>(smem + (it & 1) * 2 * GSTG);
        const uint32_t* bs = as + GSTG;

        #pragma unroll
        for (int ks = 0; ks < 4; ks++) {
            const int kk = ks * 8;
            uint32_t af[4][4], bf[4][2];
            #pragma unroll
            for (int mf = 0; mf < 4; mf++) {
                const int r = wm + mf * 16 + gid;
                af[mf][0] = as[r       * 36 + kk + ctid];
                af[mf][1] = as[(r + 8) * 36 + kk + ctid];
                af[mf][2] = as[r       * 36 + kk + ctid + 4];
                af[mf][3] = as[(r + 8) * 36 + kk + ctid + 4];
            }
            #pragma unroll
            for (int nf = 0; nf < 4; nf++) {
                const int c = wn + nf * 8 + gid;
                bf[nf][0] = bs[c * 36 + kk + ctid];
                bf[nf][1] = bs[c * 36 + kk + ctid + 4];
            }
            #pragma unroll
            for (int mf = 0; mf < 4; mf++)
                #pragma unroll
                for (int nf = 0; nf < 4; nf++)
                    mma_tf32(acc[mf][nf], af[mf], bf[nf]);
        }
    }

    const bool rnd = (jb.mode != MODE_PLAIN);   // Q/K/V consumed as tf32 downstream
    #pragma unroll
    for (int mf = 0; mf < 4; mf++) {
        #pragma unroll
        for (int nf = 0; nf < 4; nf++) {
            const int r0 = bm + wm + mf * 16 + gid;
            const int c0 = bn + wn + nf * 8 + 2 * ctid;
            const float b0 = jb.bias ? jb.bias[c0]     : 0.0f;
            const float b1 = jb.bias ? jb.bias[c0 + 1] : 0.0f;
            float v00 = (acc[mf][nf][0] + b0) * jb.alpha;
            float v01 = (acc[mf][nf][1] + b1) * jb.alpha;
            float v10 = (acc[mf][nf][2] + b0) * jb.alpha;
            float v11 = (acc[mf][nf][3] + b1) * jb.alpha;
            if (rnd) {
                v00 = __uint_as_float(f2tf(v00)); v01 = __uint_as_float(f2tf(v01));
                v10 = __uint_as_float(f2tf(v10)); v11 = __uint_as_float(f2tf(v11));
            }
            long long i0, i1;
            if (jb.mode == MODE_PLAIN) {
                i0 = (long long)r0 * DHID + c0;
                i1 = (long long)(r0 + 8) * DHID + c0;
            } else {
                const int h  = c0 >> 6, hd = c0 & 63;
                const int b_  = r0 / jb.S, s0 = r0 - b_ * jb.S;
                const int b_2 = (r0 + 8) / jb.S, s1 = (r0 + 8) - b_2 * jb.S;
                if (jb.mode == MODE_QSPLIT) {
                    i0 = (((long long)(b_  * NHEAD + h)) * jb.S + s0) * HDIM + hd;
                    i1 = (((long long)(b_2 * NHEAD + h)) * jb.S + s1) * HDIM + hd;
                } else {
                    i0 = (((long long)(b_  * NHEAD + h)) * SKV + jb.off + s0) * HDIM + hd;
                    i1 = (((long long)(b_2 * NHEAD + h)) * SKV + jb.off + s1) * HDIM + hd;
                }
            }
            *reinterpret_cast<float2*>(&jb.C[i0]) = make_float2(v00, v01);
            *reinterpret_cast<float2*>(&jb.C[i1]) = make_float2(v10, v11);
        }
    }
}

// ---------------- fused attention (512 threads, 128-row chunks, 2-stage) ----------------
#define CHUNK 128
#define NCH ((SKV + CHUNK - 1) / CHUNK)   // 9 (8 full + 1 of 64)
#define ATTN_SMEM ((32 * SC_STRIDE + 32 * Q_STRIDE + 2 * CHUNK * KV_STRIDE) * 4)

__global__ __launch_bounds__(512, 1) void attn_kernel(
    const float* __restrict__ Qt, const float* __restrict__ Qi,
    const float* __restrict__ Kg, const float* __restrict__ Vg,
    float* __restrict__ Wt, float* __restrict__ Wi,
    float* __restrict__ Ot, float* __restrict__ Oi)
{
    extern __shared__ char sm[];
    float* Sc = reinterpret_cast<float*>(sm);       // 32 x SC_STRIDE
    float* Qs = Sc + 32 * SC_STRIDE;                // 32 x Q_STRIDE
    float* KV = Qs + 32 * Q_STRIDE;                 // 2 x 128 x KV_STRIDE

    const bool isT = blockIdx.x < (ST / 32);
    const int  Sq  = isT ? ST : SI;
    const float* Q   = isT ? Qt : Qi;
    float* Wout      = isT ? Wt : Wi;
    float* O         = isT ? Ot : Oi;
    const int qbase  = (isT ? blockIdx.x : blockIdx.x - ST / 32) * 32;

    const int z = blockIdx.y;
    const int b = z >> 4, h = z & 15;
    const int tid  = threadIdx.x;
    const int w    = tid >> 5;
    const int lane = tid & 31;
    const int gid  = lane >> 2;
    const int ctid = lane & 3;
    const int mhalf  = w >> 3;          // phase-3 row half
    const int nstrip = (w & 7) * 8;     // phase-3 hd strip

    auto issueK = [&](int c, int s) {
        float* dst = KV + s * CHUNK * KV_STRIDE;
        const int rows = min(CHUNK, SKV - c * CHUNK);
        for (int i = tid; i < rows * 16; i += 512) {
            const int r = i >> 4, c4 = (i & 15) * 4;
            cp16(s2u(&dst[r * KV_STRIDE + c4]), &Kg[((long long)z * SKV + c * CHUNK + r) * HDIM + c4]);
        }
        cp_commit();
    };
    auto issueV = [&](int c, int s) {
        float* dst = KV + s * CHUNK * KV_STRIDE;
        const int rows = min(CHUNK, SKV - c * CHUNK);
        for (int i = tid; i < rows * 16; i += 512) {
            const int r = i >> 4, c4 = (i & 15) * 4;
            cp16(s2u(&dst[r * KV_STRIDE + c4]), &Vg[((long long)z * SKV + c * CHUNK + r) * HDIM + c4]);
        }
        cp_commit();
    };

    // group 0: Q + K chunk 0
    for (int i = tid; i < 32 * 16; i += 512) {
        const int r = i >> 4, c4 = (i & 15) * 4;
        cp16(s2u(&Qs[r * Q_STRIDE + c4]), &Q[((long long)z * Sq + qbase + r) * HDIM + c4]);
    }
    issueK(0, 0);
    cp_wait0();
    __syncthreads();

    // hoist Q fragments for all 32 rows (data pre-rounded tf32 -> raw loads)
    const uint32_t* Qsu = reinterpret_cast<const uint32_t*>(Qs);
    uint32_t qf[8][2][4];
    #pragma unroll
    for (int ks = 0; ks < 8; ks++) {
        const int kk = ks * 8;
        #pragma unroll
        for (int mf = 0; mf < 2; mf++) {
            const int r = mf * 16 + gid;
            qf[ks][mf][0] = Qsu[r       * Q_STRIDE + kk + ctid];
            qf[ks][mf][1] = Qsu[(r + 8) * Q_STRIDE + kk + ctid];
            qf[ks][mf][2] = Qsu[r       * Q_STRIDE + kk + ctid + 4];
            qf[ks][mf][3] = Qsu[(r + 8) * Q_STRIDE + kk + ctid + 4];
        }
    }

    // ---- phase 1: scores (each warp: m32 x n8 strip of the 128-col chunk) ----
    for (int c = 0; c < NCH; c++) {
        if (c > 0) { cp_wait0(); __syncthreads(); }
        if (c + 1 < NCH) issueK(c + 1, (c + 1) & 1);

        const int cw = min(CHUNK, SKV - c * CHUNK);
        const uint32_t* buf = reinterpret_cast<const uint32_t*>(KV + (c & 1) * CHUNK * KV_STRIDE);
        if (w * 8 < cw) {
            float acc[2][4];
            #pragma unroll
            for (int mf = 0; mf < 2; mf++)
                #pragma unroll
                for (int e = 0; e < 4; e++) acc[mf][e] = 0.0f;

            const int col = w * 8 + gid;
            #pragma unroll
            for (int ks = 0; ks < 8; ks++) {
                const int kk = ks * 8;
                uint32_t bf[2];
                bf[0] = buf[col * KV_STRIDE + kk + ctid];
                bf[1] = buf[col * KV_STRIDE + kk + ctid + 4];
                mma_tf32(acc[0], qf[ks][0], bf);
                mma_tf32(acc[1], qf[ks][1], bf);
            }
            const int c0 = c * CHUNK + w * 8 + 2 * ctid;
            *reinterpret_cast<float2*>(&Sc[gid        * SC_STRIDE + c0]) = make_float2(acc[0][0], acc[0][1]);
            *reinterpret_cast<float2*>(&Sc[(gid + 8)  * SC_STRIDE + c0]) = make_float2(acc[0][2], acc[0][3]);
            *reinterpret_cast<float2*>(&Sc[(gid + 16) * SC_STRIDE + c0]) = make_float2(acc[1][0], acc[1][1]);
            *reinterpret_cast<float2*>(&Sc[(gid + 24) * SC_STRIDE + c0]) = make_float2(acc[1][2], acc[1][3]);
        }
    }
    __syncthreads();   // all scores in smem; all warps done with KV buffers

    // V chunk 0 overlaps the softmax
    issueV(0, 0);

    // ---- phase 2: softmax + w write + in-place tf32 convert ----
    {
        const int r = tid >> 4, l = tid & 15;
        float mx = -1e30f;
        for (int i = l; i < SKV; i += 16) mx = fmaxf(mx, Sc[r * SC_STRIDE + i]);
        #pragma unroll
        for (int o = 8; o > 0; o >>= 1) mx = fmaxf(mx, __shfl_xor_sync(0xffffffffu, mx, o));
        float sum = 0.0f;
        for (int i = l; i < SKV; i += 16) {
            float e = __expf(Sc[r * SC_STRIDE + i] - mx);
            Sc[r * SC_STRIDE + i] = e;
            sum += e;
        }
        #pragma unroll
        for (int o = 8; o > 0; o >>= 1) sum += __shfl_xor_sync(0xffffffffu, sum, o);
        const float inv = 1.0f / sum;
        float* wrow = Wout + ((long long)z * Sq + qbase + r) * SKV;
        uint32_t* Scu = reinterpret_cast<uint32_t*>(Sc);
        for (int i = l; i < SKV; i += 16) {
            const float v = Sc[r * SC_STRIDE + i] * inv;
            wrow[i] = v;
            Scu[r * SC_STRIDE + i] = f2tf(v);
        }
    }

    // ---- phase 3: O = w · V ----
    const uint32_t* Scu = reinterpret_cast<const uint32_t*>(Sc);
    float oacc[4] = {0.0f, 0.0f, 0.0f, 0.0f};

    for (int c = 0; c < NCH; c++) {
        cp_wait0();
        __syncthreads();   // V chunk c landed; softmax visible (c==0); buffer reuse safe
        if (c + 1 < NCH) issueV(c + 1, (c + 1) & 1);

        const int cw = min(CHUNK, SKV - c * CHUNK);
        const uint32_t* buf = reinterpret_cast<const uint32_t*>(KV + (c & 1) * CHUNK * KV_STRIDE);
        const int cb = c * CHUNK;
        const int ksteps = cw >> 3;
        for (int ks = 0; ks < ksteps; ks++) {
            const int kk = ks * 8;
            uint32_t af[4], bf[2];
            const int r = mhalf * 16 + gid;
            af[0] = Scu[r       * SC_STRIDE + cb + kk + ctid];
            af[1] = Scu[(r + 8) * SC_STRIDE + cb + kk + ctid];
            af[2] = Scu[r       * SC_STRIDE + cb + kk + ctid + 4];
            af[3] = Scu[(r + 8) * SC_STRIDE + cb + kk + ctid + 4];
            bf[0] = buf[(kk + ctid)     * KV_STRIDE + nstrip + gid];
            bf[1] = buf[(kk + ctid + 4) * KV_STRIDE + nstrip + gid];
            mma_tf32(oacc, af, bf);
        }
    }

    // epilogue: head-merged O, pre-rounded tf32 (feeds the output projection)
    {
        const int r0 = qbase + mhalf * 16 + gid;
        const int c0 = h * HDIM + nstrip + 2 * ctid;
        float2 v0 = make_float2(__uint_as_float(f2tf(oacc[0])), __uint_as_float(f2tf(oacc[1])));
        float2 v1 = make_float2(__uint_as_float(f2tf(oacc[2])), __uint_as_float(f2tf(oacc[3])));
        *reinterpret_cast<float2*>(&O[((long long)b * Sq + r0) * DHID + c0])     = v0;
        *reinterpret_cast<float2*>(&O[((long long)b * Sq + r0 + 8) * DHID + c0]) = v1;
    }
}

// ---------------- host orchestration ----------------
extern "C" void kernel_launch(void* const* d_in, const int* in_sizes, int n_in,
                              void* d_out, int out_size)
{
    const float* q_text  = (const float*)d_in[0];
    const float* q_image = (const float*)d_in[1];
    const float* k_text  = (const float*)d_in[2];
    const float* k_image = (const float*)d_in[3];
    const float* Wq_t = (const float*)d_in[4];  const float* bq_t = (const float*)d_in[5];
    const float* Wk_t = (const float*)d_in[6];  const float* bk_t = (const float*)d_in[7];
    const float* Wv_t = (const float*)d_in[8];  const float* bv_t = (const float*)d_in[9];
    const float* Wq_i = (const float*)d_in[10]; const float* bq_i = (const float*)d_in[11];
    const float* Wk_i = (const float*)d_in[12]; const float* bk_i = (const float*)d_in[13];
    const float* Wv_i = (const float*)d_in[14]; const float* bv_i = (const float*)d_in[15];
    const float* lng_t = (const float*)d_in[16]; const float* lnb_t = (const float*)d_in[17];
    const float* lng_i = (const float*)d_in[18]; const float* lnb_i = (const float*)d_in[19];
    const float* Wo = (const float*)d_in[20]; const float* bo = (const float*)d_in[21];

    float* out = (float*)d_out;
    const long long OUT_T = 0;
    const long long OUT_I = (long long)BATCH * ST * DHID;
    const long long W_T   = OUT_I + (long long)BATCH * SI * DHID;
    const long long W_I   = W_T + (long long)BATCH * NHEAD * ST * SKV;

    float *pLNQT, *pLNQI, *pLNKT, *pLNKI, *pQT, *pQI, *pK, *pV, *pOT, *pOI, *pWc;
    cudaGetSymbolAddress((void**)&pLNQT, g_ln_qt);
    cudaGetSymbolAddress((void**)&pLNQI, g_ln_qi);
    cudaGetSymbolAddress((void**)&pLNKT, g_ln_kt);
    cudaGetSymbolAddress((void**)&pLNKI, g_ln_ki);
    cudaGetSymbolAddress((void**)&pQT,   g_Q_t);
    cudaGetSymbolAddress((void**)&pQI,   g_Q_i);
    cudaGetSymbolAddress((void**)&pK,    g_K);
    cudaGetSymbolAddress((void**)&pV,    g_V);
    cudaGetSymbolAddress((void**)&pOT,   g_O_t);
    cudaGetSymbolAddress((void**)&pOI,   g_O_i);
    cudaGetSymbolAddress((void**)&pWc,   g_Wc);

    const long long WSZ = (long long)DHID * DHID;
    float* cWq_t = pWc + 0 * WSZ;  float* cWk_t = pWc + 1 * WSZ;  float* cWv_t = pWc + 2 * WSZ;
    float* cWq_i = pWc + 3 * WSZ;  float* cWk_i = pWc + 4 * WSZ;  float* cWv_i = pWc + 5 * WSZ;
    float* cWo   = pWc + 6 * WSZ;

    cudaFuncSetAttribute(gemm_tf32_multi, cudaFuncAttributeMaxDynamicSharedMemorySize, GEMM_SMEM);
    cudaFuncSetAttribute(attn_kernel,     cudaFuncAttributeMaxDynamicSharedMemorySize, ATTN_SMEM);

    // 0) weight pre-round (7 jobs)
    {
        CvtBatch cb;
        cb.j[0] = { Wq_t, cWq_t }; cb.j[1] = { Wk_t, cWk_t }; cb.j[2] = { Wv_t, cWv_t };
        cb.j[3] = { Wq_i, cWq_i }; cb.j[4] = { Wk_i, cWk_i }; cb.j[5] = { Wv_i, cWv_i };
        cb.j[6] = { Wo, cWo };
        cvt_multi<<<dim3(DHID * DHID / (256 * 4), 7), 256>>>(cb);
    }

    // 1) LayerNorms (outputs pre-rounded tf32)
    {
        LnBatch lb;
        lb.j[0] = { q_text,  lng_t, lnb_t, pLNQT, BATCH * ST };
        lb.j[1] = { q_image, lng_i, lnb_i, pLNQI, BATCH * SI };
        lb.j[2] = { k_text,  lng_t, lnb_t, pLNKT, BATCH * ST };
        lb.j[3] = { k_image, lng_i, lnb_i, pLNKI, BATCH * SI };
        ln_multi<<<dim3(BATCH * SI, 4), 256>>>(lb);
    }

    // 2) Projections (one launch, 6 jobs)
    {
        GemmBatch gb;
        gb.j[0] = { pLNQT, cWq_t, pQT, bq_t, BATCH * ST, MODE_QSPLIT, ST, 0,  QSCALE };
        gb.j[1] = { pLNQI, cWq_i, pQI, bq_i, BATCH * SI, MODE_QSPLIT, SI, 0,  QSCALE };
        gb.j[2] = { pLNKT, cWk_t, pK,  bk_t, BATCH * ST, MODE_KV,     ST, 0,  1.0f };
        gb.j[3] = { pLNKI, cWk_i, pK,  bk_i, BATCH * SI, MODE_KV,     SI, ST, 1.0f };
        gb.j[4] = { pLNKT, cWv_t, pV,  bv_t, BATCH * ST, MODE_KV,     ST, 0,  1.0f };
        gb.j[5] = { pLNKI, cWv_i, pV,  bv_i, BATCH * SI, MODE_KV,     SI, ST, 1.0f };
        gemm_tf32_multi<<<dim3(DHID / 128, (BATCH * SI) / 128, 6), 256, GEMM_SMEM>>>(gb);
    }

    // 3) Fused attention
    attn_kernel<<<dim3(ST / 32 + SI / 32, BATCH * NHEAD), 512, ATTN_SMEM>>>(
        pQT, pQI, pK, pV, out + W_T, out + W_I, pOT, pOI);

    // 4) Output projection (one launch, 2 jobs)
    {
        GemmBatch gb;
        gb.j[0] = { pOT, cWo, out + OUT_T, bo, BATCH * ST, MODE_PLAIN, 0, 0, 1.0f };
        gb.j[1] = { pOI, cWo, out + OUT_I, bo, BATCH * SI, MODE_PLAIN, 0, 0, 1.0f };
        gb.j[2] = gb.j[1]; gb.j[3] = gb.j[1]; gb.j[4] = gb.j[1]; gb.j[5] = gb.j[1];
        gemm_tf32_multi<<<dim3(DHID / 128, (BATCH * SI) / 128, 2), 256, GEMM_SMEM>>>(gb);
    }

    (void)in_sizes; (void)n_in; (void)out_size;
}

// round 10
// speedup vs baseline: 4.6345x; 1.0451x over previous
#include <cuda_runtime.h>
#include <cstdint>

#define DHID  1024
#define NHEAD 16
#define HDIM  64
#define BATCH 4
#define ST    512
#define SI    576
#define SKV   1088
#define QSCALE 0.125f
#define LN_EPS 1e-5f

#define SC_STRIDE 1092   // scores row stride (floats), %32==4
#define Q_STRIDE  68     // Q staging stride, %32==4
#define KV_STRIDE 72     // K/V chunk stride, %32==8

// ---------------- scratch (device globals; allocation-free) ----------------
__device__ float g_ln_qt[BATCH * ST * DHID];
__device__ float g_ln_qi[BATCH * SI * DHID];
__device__ float g_ln_kt[BATCH * ST * DHID];
__device__ float g_ln_ki[BATCH * SI * DHID];
__device__ float g_Q_t[BATCH * NHEAD * ST * HDIM];
__device__ float g_Q_i[BATCH * NHEAD * SI * HDIM];
__device__ float g_K  [BATCH * NHEAD * SKV * HDIM];
__device__ float g_V  [BATCH * NHEAD * SKV * HDIM];
__device__ float g_O_t[BATCH * ST * DHID];
__device__ float g_O_i[BATCH * SI * DHID];
__device__ float g_Wc [7 * DHID * DHID];   // pre-rounded tf32 weights

// ---------------- helpers ----------------
__device__ __forceinline__ uint32_t f2tf(float f) {
    uint32_t u; asm("cvt.rna.tf32.f32 %0, %1;" : "=r"(u) : "f"(f)); return u;
}
__device__ __forceinline__ void mma_tf32(float* d, const uint32_t* a, const uint32_t* b) {
    asm volatile("mma.sync.aligned.m16n8k8.row.col.f32.tf32.tf32.f32 "
                 "{%0,%1,%2,%3}, {%4,%5,%6,%7}, {%8,%9}, {%0,%1,%2,%3};"
                 : "+f"(d[0]), "+f"(d[1]), "+f"(d[2]), "+f"(d[3])
                 : "r"(a[0]), "r"(a[1]), "r"(a[2]), "r"(a[3]), "r"(b[0]), "r"(b[1]));
}
__device__ __forceinline__ uint32_t s2u(const void* p) {
    return (uint32_t)__cvta_generic_to_shared(p);
}
__device__ __forceinline__ void cp16(uint32_t dst, const void* src) {
    asm volatile("cp.async.cg.shared.global [%0], [%1], 16;" :: "r"(dst), "l"(src));
}
__device__ __forceinline__ void cp_commit() {
    asm volatile("cp.async.commit_group;");
}
__device__ __forceinline__ void cp_wait0() {
    asm volatile("cp.async.wait_group 0;" ::: "memory");
}
__device__ __forceinline__ void cp_wait1() {
    asm volatile("cp.async.wait_group 1;" ::: "memory");
}

// ---------------- tf32 pre-round for weights (7 jobs, one launch) ----------------
struct CvtJob { const float* in; float* out; };
struct CvtBatch { CvtJob j[7]; };

__global__ __launch_bounds__(256) void cvt_multi(CvtBatch batch)
{
    const CvtJob jb = batch.j[blockIdx.y];
    const int i = blockIdx.x * 256 + threadIdx.x;     // float4 index
    float4 v = reinterpret_cast<const float4*>(jb.in)[i];
    uint4 u = make_uint4(f2tf(v.x), f2tf(v.y), f2tf(v.z), f2tf(v.w));
    reinterpret_cast<uint4*>(jb.out)[i] = u;
}

// ---------------- LayerNorm (4 jobs; output pre-rounded tf32) ----------------
struct LnJob { const float* x; const float* g; const float* b; float* y; int rows; };
struct LnBatch { LnJob j[4]; };

__global__ __launch_bounds__(256) void ln_multi(LnBatch batch)
{
    const LnJob jb = batch.j[blockIdx.y];
    const int row = blockIdx.x;
    if (row >= jb.rows) return;
    const int t = threadIdx.x;
    const float4 xv = reinterpret_cast<const float4*>(jb.x + (long long)row * DHID)[t];

    float s  = xv.x + xv.y + xv.z + xv.w;
    float sq = xv.x * xv.x + xv.y * xv.y + xv.z * xv.z + xv.w * xv.w;

    __shared__ float red_s[8], red_q[8];
    #pragma unroll
    for (int o = 16; o > 0; o >>= 1) {
        s  += __shfl_xor_sync(0xffffffffu, s,  o);
        sq += __shfl_xor_sync(0xffffffffu, sq, o);
    }
    if ((t & 31) == 0) { red_s[t >> 5] = s; red_q[t >> 5] = sq; }
    __syncthreads();
    float ts = red_s[t & 7], tq = red_q[t & 7];
    #pragma unroll
    for (int o = 4; o > 0; o >>= 1) {
        ts += __shfl_xor_sync(0xffffffffu, ts, o);
        tq += __shfl_xor_sync(0xffffffffu, tq, o);
    }
    ts = __shfl_sync(0xffffffffu, ts, 0);
    tq = __shfl_sync(0xffffffffu, tq, 0);

    const float mean = ts * (1.0f / DHID);
    const float rstd = rsqrtf(tq * (1.0f / DHID) - mean * mean + LN_EPS);

    const float4 gv = reinterpret_cast<const float4*>(jb.g)[t];
    const float4 bv = reinterpret_cast<const float4*>(jb.b)[t];
    uint4 o;
    o.x = f2tf((xv.x - mean) * rstd * gv.x + bv.x);
    o.y = f2tf((xv.y - mean) * rstd * gv.y + bv.y);
    o.z = f2tf((xv.z - mean) * rstd * gv.z + bv.z);
    o.w = f2tf((xv.w - mean) * rstd * gv.w + bv.w);
    reinterpret_cast<uint4*>(jb.y + (long long)row * DHID)[t] = o;
}

// ---------------- batched tf32 GEMM (3-stage cp.async; no inner cvt) ----------------
#define MODE_PLAIN  0   // fp32 store (final outputs)
#define MODE_QSPLIT 1   // tf32-rounded store
#define MODE_KV     2   // tf32-rounded store

struct GemmJob {
    const float* A; const float* Bt; float* C; const float* bias;
    int M; int mode; int S; int off; float alpha;
};
struct GemmBatch { GemmJob j[6]; };

#define GSTG (128 * 36)
#define GEMM_SMEM (6 * GSTG * 4)   // 3 stages x (A+B) = 110592 bytes

__global__ __launch_bounds__(256, 2) void gemm_tf32_multi(GemmBatch batch)
{
    extern __shared__ float smem[];
    const GemmJob jb = batch.j[blockIdx.z];
    const int bm = blockIdx.y * 128;
    if (bm >= jb.M) return;
    const int bn = blockIdx.x * 128;

    const int tid  = threadIdx.x;
    const int w    = tid >> 5;
    const int lane = tid & 31;
    const int gid  = lane >> 2;
    const int ctid = lane & 3;
    const int wm = (w & 1) * 64;
    const int wn = (w >> 1) * 32;
    const int lr = tid >> 3;
    const int lc = (tid & 7) * 4;

    const float* A  = jb.A;
    const float* Bt = jb.Bt;

    auto issue = [&](int k0, int s) {
        float* as = smem + s * 2 * GSTG;
        float* bs = as + GSTG;
        #pragma unroll
        for (int p = 0; p < 4; p++) {
            cp16(s2u(&as[(lr + p * 32) * 36 + lc]), &A [(long long)(bm + lr + p * 32) * DHID + k0 + lc]);
            cp16(s2u(&bs[(lr + p * 32) * 36 + lc]), &Bt[(long long)(bn + lr + p * 32) * DHID + k0 + lc]);
        }
        cp_commit();
    };

    float acc[4][4][4];
    #pragma unroll
    for (int i = 0; i < 4; i++)
        #pragma unroll
        for (int j = 0; j < 4; j++)
            #pragma unroll
            for (int e = 0; e < 4; e++) acc[i][j][e] = 0.0f;

    issue(0, 0);
    issue(32, 1);

    for (int it = 0; it < 32; it++) {
        if (it == 31) cp_wait0(); else cp_wait1();   // tail-aware drain
        __syncthreads();
        if (it + 2 < 32) issue((it + 2) * 32, (it + 2) % 3);

        const uint32_t* as = reinterpret_cast<const uint32_t*>(smem + (it % 3) * 2 * GSTG);
        const uint32_t* bs = as + GSTG;

        #pragma unroll
        for (int ks = 0; ks < 4; ks++) {
            const int kk = ks * 8;
            uint32_t af[4][4], bf[4][2];
            #pragma unroll
            for (int mf = 0; mf < 4; mf++) {
                const int r = wm + mf * 16 + gid;
                af[mf][0] = as[r       * 36 + kk + ctid];
                af[mf][1] = as[(r + 8) * 36 + kk + ctid];
                af[mf][2] = as[r       * 36 + kk + ctid + 4];
                af[mf][3] = as[(r + 8) * 36 + kk + ctid + 4];
            }
            #pragma unroll
            for (int nf = 0; nf < 4; nf++) {
                const int c = wn + nf * 8 + gid;
                bf[nf][0] = bs[c * 36 + kk + ctid];
                bf[nf][1] = bs[c * 36 + kk + ctid + 4];
            }
            #pragma unroll
            for (int mf = 0; mf < 4; mf++)
                #pragma unroll
                for (int nf = 0; nf < 4; nf++)
                    mma_tf32(acc[mf][nf], af[mf], bf[nf]);
        }
    }

    const bool rnd = (jb.mode != MODE_PLAIN);   // Q/K/V consumed as tf32 downstream
    #pragma unroll
    for (int mf = 0; mf < 4; mf++) {
        #pragma unroll
        for (int nf = 0; nf < 4; nf++) {
            const int r0 = bm + wm + mf * 16 + gid;
            const int c0 = bn + wn + nf * 8 + 2 * ctid;
            const float b0 = jb.bias ? jb.bias[c0]     : 0.0f;
            const float b1 = jb.bias ? jb.bias[c0 + 1] : 0.0f;
            float v00 = (acc[mf][nf][0] + b0) * jb.alpha;
            float v01 = (acc[mf][nf][1] + b1) * jb.alpha;
            float v10 = (acc[mf][nf][2] + b0) * jb.alpha;
            float v11 = (acc[mf][nf][3] + b1) * jb.alpha;
            if (rnd) {
                v00 = __uint_as_float(f2tf(v00)); v01 = __uint_as_float(f2tf(v01));
                v10 = __uint_as_float(f2tf(v10)); v11 = __uint_as_float(f2tf(v11));
            }
            long long i0, i1;
            if (jb.mode == MODE_PLAIN) {
                i0 = (long long)r0 * DHID + c0;
                i1 = (long long)(r0 + 8) * DHID + c0;
            } else {
                const int h  = c0 >> 6, hd = c0 & 63;
                const int b_  = r0 / jb.S, s0 = r0 - b_ * jb.S;
                const int b_2 = (r0 + 8) / jb.S, s1 = (r0 + 8) - b_2 * jb.S;
                if (jb.mode == MODE_QSPLIT) {
                    i0 = (((long long)(b_  * NHEAD + h)) * jb.S + s0) * HDIM + hd;
                    i1 = (((long long)(b_2 * NHEAD + h)) * jb.S + s1) * HDIM + hd;
                } else {
                    i0 = (((long long)(b_  * NHEAD + h)) * SKV + jb.off + s0) * HDIM + hd;
                    i1 = (((long long)(b_2 * NHEAD + h)) * SKV + jb.off + s1) * HDIM + hd;
                }
            }
            *reinterpret_cast<float2*>(&jb.C[i0]) = make_float2(v00, v01);
            *reinterpret_cast<float2*>(&jb.C[i1]) = make_float2(v10, v11);
        }
    }
}

// ---------------- fused attention (512 threads, 128-row chunks, 2-stage) ----------------
#define CHUNK 128
#define NCH ((SKV + CHUNK - 1) / CHUNK)   // 9 (8 full + 1 of 64)
#define ATTN_SMEM ((32 * SC_STRIDE + 32 * Q_STRIDE + 2 * CHUNK * KV_STRIDE) * 4)

__global__ __launch_bounds__(512, 1) void attn_kernel(
    const float* __restrict__ Qt, const float* __restrict__ Qi,
    const float* __restrict__ Kg, const float* __restrict__ Vg,
    float* __restrict__ Wt, float* __restrict__ Wi,
    float* __restrict__ Ot, float* __restrict__ Oi)
{
    extern __shared__ char sm[];
    float* Sc = reinterpret_cast<float*>(sm);       // 32 x SC_STRIDE
    float* Qs = Sc + 32 * SC_STRIDE;                // 32 x Q_STRIDE
    float* KV = Qs + 32 * Q_STRIDE;                 // 2 x 128 x KV_STRIDE

    const bool isT = blockIdx.x < (ST / 32);
    const int  Sq  = isT ? ST : SI;
    const float* Q   = isT ? Qt : Qi;
    float* Wout      = isT ? Wt : Wi;
    float* O         = isT ? Ot : Oi;
    const int qbase  = (isT ? blockIdx.x : blockIdx.x - ST / 32) * 32;

    const int z = blockIdx.y;
    const int b = z >> 4, h = z & 15;
    const int tid  = threadIdx.x;
    const int w    = tid >> 5;
    const int lane = tid & 31;
    const int gid  = lane >> 2;
    const int ctid = lane & 3;

    auto issueK = [&](int c, int s) {
        float* dst = KV + s * CHUNK * KV_STRIDE;
        const int rows = min(CHUNK, SKV - c * CHUNK);
        for (int i = tid; i < rows * 16; i += 512) {
            const int r = i >> 4, c4 = (i & 15) * 4;
            cp16(s2u(&dst[r * KV_STRIDE + c4]), &Kg[((long long)z * SKV + c * CHUNK + r) * HDIM + c4]);
        }
        cp_commit();
    };
    auto issueV = [&](int c, int s) {
        float* dst = KV + s * CHUNK * KV_STRIDE;
        const int rows = min(CHUNK, SKV - c * CHUNK);
        for (int i = tid; i < rows * 16; i += 512) {
            const int r = i >> 4, c4 = (i & 15) * 4;
            cp16(s2u(&dst[r * KV_STRIDE + c4]), &Vg[((long long)z * SKV + c * CHUNK + r) * HDIM + c4]);
        }
        cp_commit();
    };

    // group 0: Q + K chunk 0
    for (int i = tid; i < 32 * 16; i += 512) {
        const int r = i >> 4, c4 = (i & 15) * 4;
        cp16(s2u(&Qs[r * Q_STRIDE + c4]), &Q[((long long)z * Sq + qbase + r) * HDIM + c4]);
    }
    issueK(0, 0);
    cp_wait0();
    __syncthreads();

    // hoist Q fragments for all 32 rows (pre-rounded tf32 -> raw loads)
    const uint32_t* Qsu = reinterpret_cast<const uint32_t*>(Qs);
    uint32_t qf[8][2][4];
    #pragma unroll
    for (int ks = 0; ks < 8; ks++) {
        const int kk = ks * 8;
        #pragma unroll
        for (int mf = 0; mf < 2; mf++) {
            const int r = mf * 16 + gid;
            qf[ks][mf][0] = Qsu[r       * Q_STRIDE + kk + ctid];
            qf[ks][mf][1] = Qsu[(r + 8) * Q_STRIDE + kk + ctid];
            qf[ks][mf][2] = Qsu[r       * Q_STRIDE + kk + ctid + 4];
            qf[ks][mf][3] = Qsu[(r + 8) * Q_STRIDE + kk + ctid + 4];
        }
    }

    // ---- phase 1: scores (each warp: m32 x n8 strip of the 128-col chunk) ----
    for (int c = 0; c < NCH; c++) {
        if (c > 0) { cp_wait0(); __syncthreads(); }
        if (c + 1 < NCH) issueK(c + 1, (c + 1) & 1);

        const int cw = min(CHUNK, SKV - c * CHUNK);
        const uint32_t* buf = reinterpret_cast<const uint32_t*>(KV + (c & 1) * CHUNK * KV_STRIDE);
        if (w * 8 < cw) {
            float acc[2][4];
            #pragma unroll
            for (int mf = 0; mf < 2; mf++)
                #pragma unroll
                for (int e = 0; e < 4; e++) acc[mf][e] = 0.0f;

            const int col = w * 8 + gid;
            #pragma unroll
            for (int ks = 0; ks < 8; ks++) {
                const int kk = ks * 8;
                uint32_t bf[2];
                bf[0] = buf[col * KV_STRIDE + kk + ctid];
                bf[1] = buf[col * KV_STRIDE + kk + ctid + 4];
                mma_tf32(acc[0], qf[ks][0], bf);
                mma_tf32(acc[1], qf[ks][1], bf);
            }
            const int c0 = c * CHUNK + w * 8 + 2 * ctid;
            *reinterpret_cast<float2*>(&Sc[gid        * SC_STRIDE + c0]) = make_float2(acc[0][0], acc[0][1]);
            *reinterpret_cast<float2*>(&Sc[(gid + 8)  * SC_STRIDE + c0]) = make_float2(acc[0][2], acc[0][3]);
            *reinterpret_cast<float2*>(&Sc[(gid + 16) * SC_STRIDE + c0]) = make_float2(acc[1][0], acc[1][1]);
            *reinterpret_cast<float2*>(&Sc[(gid + 24) * SC_STRIDE + c0]) = make_float2(acc[1][2], acc[1][3]);
        }
    }
    __syncthreads();   // all scores in smem; all warps done with KV buffers

    // V chunk 0 overlaps the softmax
    issueV(0, 0);

    // ---- phase 2: softmax + w write + in-place tf32 convert ----
    {
        const int r = tid >> 4, l = tid & 15;
        float mx = -1e30f;
        for (int i = l; i < SKV; i += 16) mx = fmaxf(mx, Sc[r * SC_STRIDE + i]);
        #pragma unroll
        for (int o = 8; o > 0; o >>= 1) mx = fmaxf(mx, __shfl_xor_sync(0xffffffffu, mx, o));
        float sum = 0.0f;
        for (int i = l; i < SKV; i += 16) {
            float e = __expf(Sc[r * SC_STRIDE + i] - mx);
            Sc[r * SC_STRIDE + i] = e;
            sum += e;
        }
        #pragma unroll
        for (int o = 8; o > 0; o >>= 1) sum += __shfl_xor_sync(0xffffffffu, sum, o);
        const float inv = 1.0f / sum;
        float* wrow = Wout + ((long long)z * Sq + qbase + r) * SKV;
        uint32_t* Scu = reinterpret_cast<uint32_t*>(Sc);
        for (int i = l; i < SKV; i += 16) {
            const float v = Sc[r * SC_STRIDE + i] * inv;
            wrow[i] = v;
            Scu[r * SC_STRIDE + i] = f2tf(v);
        }
    }

    // ---- phase 3: O = w · V ----
    // warp grid: mtile(2) x nhalf(2) x kslice(4). Each warp: m16 x n32, 1/4 of K
    // (interleaved at ks granularity within each chunk). Score-fragment loads
    // drop 4x vs the n-strip layout; partials reduced through smem at the end.
    const uint32_t* Scu = reinterpret_cast<const uint32_t*>(Sc);
    const int mtile  = w & 1;
    const int nhalf  = (w >> 1) & 1;
    const int kslice = w >> 2;          // 0..3
    float acc[4][4];
    #pragma unroll
    for (int nf = 0; nf < 4; nf++)
        #pragma unroll
        for (int e = 0; e < 4; e++) acc[nf][e] = 0.0f;

    for (int c = 0; c < NCH; c++) {
        cp_wait0();
        __syncthreads();   // V chunk c landed; softmax visible (c==0); buffer reuse safe
        if (c + 1 < NCH) issueV(c + 1, (c + 1) & 1);

        const int cw = min(CHUNK, SKV - c * CHUNK);
        const uint32_t* buf = reinterpret_cast<const uint32_t*>(KV + (c & 1) * CHUNK * KV_STRIDE);
        const int cb = c * CHUNK;
        const int per = cw >> 5;        // ks-steps per kslice: 4 (full) or 2 (tail)
        const int r = mtile * 16 + gid;
        for (int j = 0; j < per; j++) {
            const int kk = (kslice * per + j) * 8;
            uint32_t af[4];
            af[0] = Scu[r       * SC_STRIDE + cb + kk + ctid];
            af[1] = Scu[(r + 8) * SC_STRIDE + cb + kk + ctid];
            af[2] = Scu[r       * SC_STRIDE + cb + kk + ctid + 4];
            af[3] = Scu[(r + 8) * SC_STRIDE + cb + kk + ctid + 4];
            #pragma unroll
            for (int nf = 0; nf < 4; nf++) {
                uint32_t bf[2];
                const int col = nhalf * 32 + nf * 8 + gid;
                bf[0] = buf[(kk + ctid)     * KV_STRIDE + col];
                bf[1] = buf[(kk + ctid + 4) * KV_STRIDE + col];
                mma_tf32(acc[nf], af, bf);
            }
        }
    }

    // ---- kslice reduction (reuse Sc region; padded stride 17) ----
    __syncthreads();   // all phase-3 reads of Sc/KV done
    float* red = Sc;
    const int rbase = (w * 32 + lane) * 17;
    #pragma unroll
    for (int nf = 0; nf < 4; nf++)
        #pragma unroll
        for (int e = 0; e < 4; e++) red[rbase + nf * 4 + e] = acc[nf][e];
    __syncthreads();

    if (kslice == 0) {
        #pragma unroll
        for (int nf = 0; nf < 4; nf++)
            #pragma unroll
            for (int e = 0; e < 4; e++)
                acc[nf][e] += red[((w + 4)  * 32 + lane) * 17 + nf * 4 + e]
                            + red[((w + 8)  * 32 + lane) * 17 + nf * 4 + e]
                            + red[((w + 12) * 32 + lane) * 17 + nf * 4 + e];

        // epilogue: head-merged O, pre-rounded tf32 (feeds output projection)
        const int r0 = qbase + mtile * 16 + gid;
        #pragma unroll
        for (int nf = 0; nf < 4; nf++) {
            const int c0 = h * HDIM + nhalf * 32 + nf * 8 + 2 * ctid;
            float2 v0 = make_float2(__uint_as_float(f2tf(acc[nf][0])), __uint_as_float(f2tf(acc[nf][1])));
            float2 v1 = make_float2(__uint_as_float(f2tf(acc[nf][2])), __uint_as_float(f2tf(acc[nf][3])));
            *reinterpret_cast<float2*>(&O[((long long)b * Sq + r0) * DHID + c0])     = v0;
            *reinterpret_cast<float2*>(&O[((long long)b * Sq + r0 + 8) * DHID + c0]) = v1;
        }
    }
}

// ---------------- host orchestration ----------------
extern "C" void kernel_launch(void* const* d_in, const int* in_sizes, int n_in,
                              void* d_out, int out_size)
{
    const float* q_text  = (const float*)d_in[0];
    const float* q_image = (const float*)d_in[1];
    const float* k_text  = (const float*)d_in[2];
    const float* k_image = (const float*)d_in[3];
    const float* Wq_t = (const float*)d_in[4];  const float* bq_t = (const float*)d_in[5];
    const float* Wk_t = (const float*)d_in[6];  const float* bk_t = (const float*)d_in[7];
    const float* Wv_t = (const float*)d_in[8];  const float* bv_t = (const float*)d_in[9];
    const float* Wq_i = (const float*)d_in[10]; const float* bq_i = (const float*)d_in[11];
    const float* Wk_i = (const float*)d_in[12]; const float* bk_i = (const float*)d_in[13];
    const float* Wv_i = (const float*)d_in[14]; const float* bv_i = (const float*)d_in[15];
    const float* lng_t = (const float*)d_in[16]; const float* lnb_t = (const float*)d_in[17];
    const float* lng_i = (const float*)d_in[18]; const float* lnb_i = (const float*)d_in[19];
    const float* Wo = (const float*)d_in[20]; const float* bo = (const float*)d_in[21];

    float* out = (float*)d_out;
    const long long OUT_T = 0;
    const long long OUT_I = (long long)BATCH * ST * DHID;
    const long long W_T   = OUT_I + (long long)BATCH * SI * DHID;
    const long long W_I   = W_T + (long long)BATCH * NHEAD * ST * SKV;

    float *pLNQT, *pLNQI, *pLNKT, *pLNKI, *pQT, *pQI, *pK, *pV, *pOT, *pOI, *pWc;
    cudaGetSymbolAddress((void**)&pLNQT, g_ln_qt);
    cudaGetSymbolAddress((void**)&pLNQI, g_ln_qi);
    cudaGetSymbolAddress((void**)&pLNKT, g_ln_kt);
    cudaGetSymbolAddress((void**)&pLNKI, g_ln_ki);
    cudaGetSymbolAddress((void**)&pQT,   g_Q_t);
    cudaGetSymbolAddress((void**)&pQI,   g_Q_i);
    cudaGetSymbolAddress((void**)&pK,    g_K);
    cudaGetSymbolAddress((void**)&pV,    g_V);
    cudaGetSymbolAddress((void**)&pOT,   g_O_t);
    cudaGetSymbolAddress((void**)&pOI,   g_O_i);
    cudaGetSymbolAddress((void**)&pWc,   g_Wc);

    const long long WSZ = (long long)DHID * DHID;
    float* cWq_t = pWc + 0 * WSZ;  float* cWk_t = pWc + 1 * WSZ;  float* cWv_t = pWc + 2 * WSZ;
    float* cWq_i = pWc + 3 * WSZ;  float* cWk_i = pWc + 4 * WSZ;  float* cWv_i = pWc + 5 * WSZ;
    float* cWo   = pWc + 6 * WSZ;

    cudaFuncSetAttribute(gemm_tf32_multi, cudaFuncAttributeMaxDynamicSharedMemorySize, GEMM_SMEM);
    cudaFuncSetAttribute(attn_kernel,     cudaFuncAttributeMaxDynamicSharedMemorySize, ATTN_SMEM);

    // 0) weight pre-round (7 jobs)
    {
        CvtBatch cb;
        cb.j[0] = { Wq_t, cWq_t }; cb.j[1] = { Wk_t, cWk_t }; cb.j[2] = { Wv_t, cWv_t };
        cb.j[3] = { Wq_i, cWq_i }; cb.j[4] = { Wk_i, cWk_i }; cb.j[5] = { Wv_i, cWv_i };
        cb.j[6] = { Wo, cWo };
        cvt_multi<<<dim3(DHID * DHID / (256 * 4), 7), 256>>>(cb);
    }

    // 1) LayerNorms (outputs pre-rounded tf32)
    {
        LnBatch lb;
        lb.j[0] = { q_text,  lng_t, lnb_t, pLNQT, BATCH * ST };
        lb.j[1] = { q_image, lng_i, lnb_i, pLNQI, BATCH * SI };
        lb.j[2] = { k_text,  lng_t, lnb_t, pLNKT, BATCH * ST };
        lb.j[3] = { k_image, lng_i, lnb_i, pLNKI, BATCH * SI };
        ln_multi<<<dim3(BATCH * SI, 4), 256>>>(lb);
    }

    // 2) Projections (one launch, 6 jobs)
    {
        GemmBatch gb;
        gb.j[0] = { pLNQT, cWq_t, pQT, bq_t, BATCH * ST, MODE_QSPLIT, ST, 0,  QSCALE };
        gb.j[1] = { pLNQI, cWq_i, pQI, bq_i, BATCH * SI, MODE_QSPLIT, SI, 0,  QSCALE };
        gb.j[2] = { pLNKT, cWk_t, pK,  bk_t, BATCH * ST, MODE_KV,     ST, 0,  1.0f };
        gb.j[3] = { pLNKI, cWk_i, pK,  bk_i, BATCH * SI, MODE_KV,     SI, ST, 1.0f };
        gb.j[4] = { pLNKT, cWv_t, pV,  bv_t, BATCH * ST, MODE_KV,     ST, 0,  1.0f };
        gb.j[5] = { pLNKI, cWv_i, pV,  bv_i, BATCH * SI, MODE_KV,     SI, ST, 1.0f };
        gemm_tf32_multi<<<dim3(DHID / 128, (BATCH * SI) / 128, 6), 256, GEMM_SMEM>>>(gb);
    }

    // 3) Fused attention
    attn_kernel<<<dim3(ST / 32 + SI / 32, BATCH * NHEAD), 512, ATTN_SMEM>>>(
        pQT, pQI, pK, pV, out + W_T, out + W_I, pOT, pOI);

    // 4) Output projection (one launch, 2 jobs)
    {
        GemmBatch gb;
        gb.j[0] = { pOT, cWo, out + OUT_T, bo, BATCH * ST, MODE_PLAIN, 0, 0, 1.0f };
        gb.j[1] = { pOI, cWo, out + OUT_I, bo, BATCH * SI, MODE_PLAIN, 0, 0, 1.0f };
        gb.j[2] = gb.j[1]; gb.j[3] = gb.j[1]; gb.j[4] = gb.j[1]; gb.j[5] = gb.j[1];
        gemm_tf32_multi<<<dim3(DHID / 128, (BATCH * SI) / 128, 2), 256, GEMM_SMEM>>>(gb);
    }

    (void)in_sizes; (void)n_in; (void)out_size;
}